// round 1
// baseline (speedup 1.0000x reference)
#include <cuda_runtime.h>
#include <cuda_bf16.h>
#include <cstdint>

// ============================================================================
// GatedGCN: 2 layers of  out = sigmoid(spmm(adj, x@G)) * spmm(adj, x@W)
//   layer1: relu(...), dims 256->256 ; layer2: no relu, dims 256->128
// N=50000 nodes, E=800000 edges (COO, unsorted -> atomic scatter).
// ============================================================================

#define N_NODES 50000
#define E_EDGES 800000
#define D_IN    256
#define D_HID   256
#define D_OUT   128

// ---------------------------------------------------------------------------
// Scratch (static device globals: allocation-free rule)
// ---------------------------------------------------------------------------
__device__ float g_support[(size_t)N_NODES * D_HID];  // gemm out S / layer2 agg S
__device__ float g_gate   [(size_t)N_NODES * D_HID];  // gemm out T / layer2 agg T
__device__ float g_aggS   [(size_t)N_NODES * D_HID];  // layer1 agg S / layer2 gemm S
__device__ float g_aggT   [(size_t)N_NODES * D_HID];  // layer1 agg T / layer2 gemm T
__device__ float g_h      [(size_t)N_NODES * D_HID];  // hidden activation

// ---------------------------------------------------------------------------
// SGEMM: C[M,N] = A[M,K] @ B[K,N], fp32, BM=128 BN=64 BK=16, 256 thr, 8x4/thr
// ---------------------------------------------------------------------------
__global__ __launch_bounds__(256) void sgemm_kernel(
    const float* __restrict__ A, const float* __restrict__ B,
    float* __restrict__ C, int M, int K, int N)
{
    constexpr int BM = 128, BN = 64, BK = 16;
    __shared__ float As[BK][BM];   // transposed A tile
    __shared__ float Bs[BK][BN];

    const int tid  = threadIdx.x;
    const int row0 = blockIdx.y * BM;
    const int col0 = blockIdx.x * BN;
    const int tx   = tid & 15;   // -> 4 cols
    const int ty   = tid >> 4;   // -> 8 rows

    float acc[8][4];
#pragma unroll
    for (int i = 0; i < 8; i++)
#pragma unroll
        for (int j = 0; j < 4; j++) acc[i][j] = 0.f;

    for (int k0 = 0; k0 < K; k0 += BK) {
        // --- load A tile: 128x16 = 512 float4, 2 per thread, store transposed
#pragma unroll
        for (int i = 0; i < 2; i++) {
            int idx = tid + i * 256;
            int ar  = idx >> 2;          // 0..127
            int ak  = (idx & 3) * 4;     // 0,4,8,12
            int grow = row0 + ar;
            float4 v = make_float4(0.f, 0.f, 0.f, 0.f);
            if (grow < M)
                v = *reinterpret_cast<const float4*>(&A[(size_t)grow * K + k0 + ak]);
            As[ak + 0][ar] = v.x;
            As[ak + 1][ar] = v.y;
            As[ak + 2][ar] = v.z;
            As[ak + 3][ar] = v.w;
        }
        // --- load B tile: 16x64 = 256 float4, 1 per thread
        {
            int br = tid >> 4;           // 0..15
            int bc = (tid & 15) * 4;     // 0..60
            float4 v = *reinterpret_cast<const float4*>(
                &B[(size_t)(k0 + br) * N + col0 + bc]);
            *reinterpret_cast<float4*>(&Bs[br][bc]) = v;
        }
        __syncthreads();

#pragma unroll
        for (int k = 0; k < BK; k++) {
            float4 a0 = *reinterpret_cast<const float4*>(&As[k][ty * 8]);
            float4 a1 = *reinterpret_cast<const float4*>(&As[k][ty * 8 + 4]);
            float4 b  = *reinterpret_cast<const float4*>(&Bs[k][tx * 4]);
            float ar[8] = {a0.x, a0.y, a0.z, a0.w, a1.x, a1.y, a1.z, a1.w};
            float br[4] = {b.x, b.y, b.z, b.w};
#pragma unroll
            for (int i = 0; i < 8; i++)
#pragma unroll
                for (int j = 0; j < 4; j++)
                    acc[i][j] = fmaf(ar[i], br[j], acc[i][j]);
        }
        __syncthreads();
    }

#pragma unroll
    for (int i = 0; i < 8; i++) {
        int grow = row0 + ty * 8 + i;
        if (grow < M) {
            float4 v = make_float4(acc[i][0], acc[i][1], acc[i][2], acc[i][3]);
            *reinterpret_cast<float4*>(&C[(size_t)grow * N + col0 + tx * 4]) = v;
        }
    }
}

// ---------------------------------------------------------------------------
// Fused dual SpMM: for each edge e, out?[rows[e]] += vals[e] * in?[cols[e]]
// for BOTH support (S) and gate (T). D4 = row width in float4 (64 or 32).
// Vectorized float4 atomicAdd (sm_90+). Accumulators fit in L2.
// ---------------------------------------------------------------------------
template <int D4>
__global__ __launch_bounds__(256) void spmm_dual_kernel(
    const int*   __restrict__ rows, const int* __restrict__ cols,
    const float* __restrict__ vals,
    const float4* __restrict__ S, const float4* __restrict__ T,
    float4* __restrict__ outS, float4* __restrict__ outT, int E)
{
    constexpr int EPB = 256 / D4;   // edges per block
    const int e = blockIdx.x * EPB + (threadIdx.x / D4);
    const int j = threadIdx.x & (D4 - 1);
    if (e >= E) return;

    const int   r = __ldg(&rows[e]);
    const int   c = __ldg(&cols[e]);
    const float v = __ldg(&vals[e]);

    const float4 s = __ldg(&S[c * D4 + j]);
    const float4 t = __ldg(&T[c * D4 + j]);

    float4 ms = make_float4(v * s.x, v * s.y, v * s.z, v * s.w);
    float4 mt = make_float4(v * t.x, v * t.y, v * t.z, v * t.w);

    atomicAdd(&outS[r * D4 + j], ms);
    atomicAdd(&outT[r * D4 + j], mt);
}

// ---------------------------------------------------------------------------
// Elementwise epilogues
// ---------------------------------------------------------------------------
__device__ __forceinline__ float sigmoidf_(float x) {
    return 1.f / (1.f + expf(-x));
}

__global__ __launch_bounds__(256) void gated_relu_kernel(
    const float4* __restrict__ S, const float4* __restrict__ T,
    float4* __restrict__ O, int n4)
{
    int i = blockIdx.x * blockDim.x + threadIdx.x;
    if (i >= n4) return;
    float4 s = S[i], t = T[i], o;
    o.x = fmaxf(sigmoidf_(t.x) * s.x, 0.f);
    o.y = fmaxf(sigmoidf_(t.y) * s.y, 0.f);
    o.z = fmaxf(sigmoidf_(t.z) * s.z, 0.f);
    o.w = fmaxf(sigmoidf_(t.w) * s.w, 0.f);
    O[i] = o;
}

__global__ __launch_bounds__(256) void gated_kernel(
    const float4* __restrict__ S, const float4* __restrict__ T,
    float4* __restrict__ O, int n4)
{
    int i = blockIdx.x * blockDim.x + threadIdx.x;
    if (i >= n4) return;
    float4 s = S[i], t = T[i], o;
    o.x = sigmoidf_(t.x) * s.x;
    o.y = sigmoidf_(t.y) * s.y;
    o.z = sigmoidf_(t.z) * s.z;
    o.w = sigmoidf_(t.w) * s.w;
    O[i] = o;
}

// ---------------------------------------------------------------------------
// Launcher (graph-capturable: async memset + kernel launches only)
// ---------------------------------------------------------------------------
extern "C" void kernel_launch(void* const* d_in, const int* in_sizes, int n_in,
                              void* d_out, int out_size)
{
    const float* x    = (const float*)d_in[0];
    const int*   rows = (const int*)  d_in[1];
    const int*   cols = (const int*)  d_in[2];
    const float* vals = (const float*)d_in[3];
    const float* W1   = (const float*)d_in[4];
    const float* G1   = (const float*)d_in[5];
    const float* W2   = (const float*)d_in[6];
    const float* G2   = (const float*)d_in[7];
    float* out = (float*)d_out;

    float *sup, *gat, *aggS, *aggT, *h;
    cudaGetSymbolAddress((void**)&sup,  g_support);
    cudaGetSymbolAddress((void**)&gat,  g_gate);
    cudaGetSymbolAddress((void**)&aggS, g_aggS);
    cudaGetSymbolAddress((void**)&aggT, g_aggT);
    cudaGetSymbolAddress((void**)&h,    g_h);

    const int M = N_NODES;
    const dim3 gemm_grid_hid(D_HID / 64, (M + 127) / 128);  // N=256
    const dim3 gemm_grid_out(D_OUT / 64, (M + 127) / 128);  // N=128

    // ---------------- Layer 1 (256 -> 256, relu) ----------------
    cudaMemsetAsync(aggS, 0, (size_t)M * D_HID * sizeof(float));
    cudaMemsetAsync(aggT, 0, (size_t)M * D_HID * sizeof(float));

    sgemm_kernel<<<gemm_grid_hid, 256>>>(x, W1, sup, M, D_IN, D_HID);
    sgemm_kernel<<<gemm_grid_hid, 256>>>(x, G1, gat, M, D_IN, D_HID);

    {   // D_HID=256 -> 64 float4/row, 4 edges/block
        int blocks = (E_EDGES + 3) / 4;
        spmm_dual_kernel<64><<<blocks, 256>>>(
            rows, cols, vals,
            (const float4*)sup, (const float4*)gat,
            (float4*)aggS, (float4*)aggT, E_EDGES);
    }

    {   // h = relu(sigmoid(aggT) * aggS)
        int n4 = M * (D_HID / 4);
        gated_relu_kernel<<<(n4 + 255) / 256, 256>>>(
            (const float4*)aggS, (const float4*)aggT, (float4*)h, n4);
    }

    // ---------------- Layer 2 (256 -> 128) ----------------
    // reuse: gemm outputs -> aggS/aggT ; aggregation targets -> sup/gat
    cudaMemsetAsync(sup, 0, (size_t)M * D_OUT * sizeof(float));
    cudaMemsetAsync(gat, 0, (size_t)M * D_OUT * sizeof(float));

    sgemm_kernel<<<gemm_grid_out, 256>>>(h, W2, aggS, M, D_HID, D_OUT);
    sgemm_kernel<<<gemm_grid_out, 256>>>(h, G2, aggT, M, D_HID, D_OUT);

    {   // D_OUT=128 -> 32 float4/row, 8 edges/block
        int blocks = (E_EDGES + 7) / 8;
        spmm_dual_kernel<32><<<blocks, 256>>>(
            rows, cols, vals,
            (const float4*)aggS, (const float4*)aggT,
            (float4*)sup, (float4*)gat, E_EDGES);
    }

    {   // out = sigmoid(gat) * sup
        int n4 = M * (D_OUT / 4);
        gated_kernel<<<(n4 + 255) / 256, 256>>>(
            (const float4*)sup, (const float4*)gat, (float4*)out, n4);
    }
}

// round 2
// speedup vs baseline: 1.3461x; 1.3461x over previous
#include <cuda_runtime.h>
#include <cuda_bf16.h>
#include <cstdint>

// ============================================================================
// GatedGCN on GB300.
//   layer: out = sigmoid(spmm(adj, x@G)) * spmm(adj, x@W); layer1 +relu
// Strategy:
//   - per-launch CSR build (counting sort) -> pull-based SpMM, NO atomics,
//     gating epilogue fused into the SpMM.
//   - SGEMM with packed fma.rn.f32x2 (FFMA2), 128x128x16 tile, 8x8/thread.
// ============================================================================

#define N_NODES 50000
#define E_EDGES 800000
#define D_IN    256
#define D_HID   256
#define D_OUT   128

// ---------------------------------------------------------------------------
// Scratch (device globals: allocation-free rule)
// ---------------------------------------------------------------------------
__device__ float g_bufA [(size_t)N_NODES * D_HID];   // gemm outputs (support)
__device__ float g_bufB [(size_t)N_NODES * D_HID];   // gemm outputs (gate)
__device__ float g_h    [(size_t)N_NODES * D_HID];   // hidden activation
__device__ int   g_rowptr[N_NODES + 1];
__device__ int   g_cnt   [N_NODES];
__device__ int2  g_edges [E_EDGES];                  // (col, val-bits) sorted by row

// ---------------------------------------------------------------------------
// f32x2 packed-FMA helpers
// ---------------------------------------------------------------------------
__device__ __forceinline__ unsigned long long pack2(float lo, float hi) {
    unsigned long long r;
    asm("mov.b64 %0, {%1, %2};" : "=l"(r) : "f"(lo), "f"(hi));
    return r;
}
__device__ __forceinline__ void fma2(unsigned long long& d,
                                     unsigned long long a, unsigned long long b) {
    asm("fma.rn.f32x2 %0, %1, %2, %3;" : "=l"(d) : "l"(a), "l"(b), "l"(d));
}
__device__ __forceinline__ float2 unpack2(unsigned long long v) {
    float2 f;
    asm("mov.b64 {%0, %1}, %2;" : "=f"(f.x), "=f"(f.y) : "l"(v));
    return f;
}

// ---------------------------------------------------------------------------
// SGEMM: C[M,N] = A[M,K] @ B[K,N]. BM=128 BN=128 BK=16, 256 thr, 8x8/thread,
// inner product via packed fma.rn.f32x2 (4 col-pairs per row).
// N must be a multiple of 128; K a multiple of 16. Row-guard on M.
// ---------------------------------------------------------------------------
__global__ __launch_bounds__(256) void sgemm_f32x2_kernel(
    const float* __restrict__ A, const float* __restrict__ B,
    float* __restrict__ C, int M, int K, int N)
{
    constexpr int BM = 128, BN = 128, BK = 16;
    __shared__ float As[BK][BM];   // transposed A tile
    __shared__ float Bs[BK][BN];

    const int tid  = threadIdx.x;
    const int row0 = blockIdx.y * BM;
    const int col0 = blockIdx.x * BN;
    const int tx   = tid & 15;    // 16 groups of 8 cols
    const int ty   = tid >> 4;    // 16 groups of 8 rows

    unsigned long long acc[8][4];
#pragma unroll
    for (int i = 0; i < 8; i++)
#pragma unroll
        for (int j = 0; j < 4; j++) acc[i][j] = 0ull;

    for (int k0 = 0; k0 < K; k0 += BK) {
        // A tile: 128x16 floats = 512 float4, 2 per thread, store transposed
#pragma unroll
        for (int i = 0; i < 2; i++) {
            int idx = tid + i * 256;
            int ar  = idx >> 2;
            int ak  = (idx & 3) * 4;
            int grow = row0 + ar;
            float4 v = make_float4(0.f, 0.f, 0.f, 0.f);
            if (grow < M)
                v = *reinterpret_cast<const float4*>(&A[(size_t)grow * K + k0 + ak]);
            As[ak + 0][ar] = v.x;
            As[ak + 1][ar] = v.y;
            As[ak + 2][ar] = v.z;
            As[ak + 3][ar] = v.w;
        }
        // B tile: 16x128 floats = 512 float4, 2 per thread
#pragma unroll
        for (int i = 0; i < 2; i++) {
            int idx = tid + i * 256;
            int br  = idx >> 5;
            int bc  = (idx & 31) * 4;
            float4 v = *reinterpret_cast<const float4*>(
                &B[(size_t)(k0 + br) * N + col0 + bc]);
            *reinterpret_cast<float4*>(&Bs[br][bc]) = v;
        }
        __syncthreads();

#pragma unroll
        for (int k = 0; k < BK; k++) {
            float4 a0 = *reinterpret_cast<const float4*>(&As[k][ty * 8]);
            float4 a1 = *reinterpret_cast<const float4*>(&As[k][ty * 8 + 4]);
            float4 b0 = *reinterpret_cast<const float4*>(&Bs[k][tx * 8]);
            float4 b1 = *reinterpret_cast<const float4*>(&Bs[k][tx * 8 + 4]);
            unsigned long long bp[4] = {
                pack2(b0.x, b0.y), pack2(b0.z, b0.w),
                pack2(b1.x, b1.y), pack2(b1.z, b1.w)
            };
            float ar8[8] = {a0.x, a0.y, a0.z, a0.w, a1.x, a1.y, a1.z, a1.w};
#pragma unroll
            for (int i = 0; i < 8; i++) {
                unsigned long long ad = pack2(ar8[i], ar8[i]);
#pragma unroll
                for (int j = 0; j < 4; j++) fma2(acc[i][j], ad, bp[j]);
            }
        }
        __syncthreads();
    }

#pragma unroll
    for (int i = 0; i < 8; i++) {
        int grow = row0 + ty * 8 + i;
        if (grow < M) {
            float2 c0 = unpack2(acc[i][0]), c1 = unpack2(acc[i][1]);
            float2 c2 = unpack2(acc[i][2]), c3 = unpack2(acc[i][3]);
            float4 lo = make_float4(c0.x, c0.y, c1.x, c1.y);
            float4 hi = make_float4(c2.x, c2.y, c3.x, c3.y);
            *reinterpret_cast<float4*>(&C[(size_t)grow * N + col0 + tx * 8])     = lo;
            *reinterpret_cast<float4*>(&C[(size_t)grow * N + col0 + tx * 8 + 4]) = hi;
        }
    }
}

// ---------------------------------------------------------------------------
// CSR build: histogram -> scan -> scatter
// ---------------------------------------------------------------------------
__global__ __launch_bounds__(256) void hist_kernel(
    const int* __restrict__ rows, int* __restrict__ cnt, int E)
{
    int e = blockIdx.x * blockDim.x + threadIdx.x;
    if (e < E) atomicAdd(&cnt[rows[e]], 1);
}

// Single-block exclusive scan over n counters -> rowptr[0..n]
__global__ __launch_bounds__(1024) void scan_kernel(
    const int* __restrict__ cnt, int* __restrict__ rowptr, int n)
{
    __shared__ int warp_sums[32];
    __shared__ int s_carry;
    const int tid = threadIdx.x;
    const int lane = tid & 31, w = tid >> 5;
    if (tid == 0) { rowptr[0] = 0; s_carry = 0; }
    __syncthreads();

    for (int base = 0; base < n; base += 1024) {
        int i = base + tid;
        int v = (i < n) ? cnt[i] : 0;
        int s = v;
#pragma unroll
        for (int o = 1; o < 32; o <<= 1) {
            int t = __shfl_up_sync(0xffffffffu, s, o);
            if (lane >= o) s += t;
        }
        if (lane == 31) warp_sums[w] = s;
        __syncthreads();
        if (w == 0) {
            int ws = warp_sums[lane];
#pragma unroll
            for (int o = 1; o < 32; o <<= 1) {
                int t = __shfl_up_sync(0xffffffffu, ws, o);
                if (lane >= o) ws += t;
            }
            warp_sums[lane] = ws;
        }
        __syncthreads();
        int incl = s + (w > 0 ? warp_sums[w - 1] : 0) + s_carry;
        if (i < n) rowptr[i + 1] = incl;
        __syncthreads();                 // everyone consumed s_carry
        if (tid == 1023) s_carry = incl; // running total (OOB lanes add 0)
        __syncthreads();
    }
}

__global__ __launch_bounds__(256) void scatter_kernel(
    const int* __restrict__ rows, const int* __restrict__ cols,
    const float* __restrict__ vals,
    const int* __restrict__ rowptr, int* __restrict__ cursor,
    int2* __restrict__ edges, int E)
{
    int e = blockIdx.x * blockDim.x + threadIdx.x;
    if (e >= E) return;
    int r = rows[e];
    int pos = rowptr[r] + atomicAdd(&cursor[r], 1);
    edges[pos] = make_int2(cols[e], __float_as_int(vals[e]));
}

// ---------------------------------------------------------------------------
// Fused CSR dual-SpMM + gating epilogue.
//   out[r] = act( sigmoid(sum v*T[c]) * (sum v*S[c]) )
// D4 = row width in float4 (64 for D=256, 32 for D=128). RELU optional.
// Each row handled by D4 threads (one float4 column chunk each); no atomics.
// ---------------------------------------------------------------------------
__device__ __forceinline__ float sigmoidf_(float x) {
    return 1.f / (1.f + expf(-x));
}

template <int D4, bool RELU>
__global__ __launch_bounds__(256) void spmm_csr_gated_kernel(
    const int*  __restrict__ rowptr, const int2* __restrict__ edges,
    const float4* __restrict__ S, const float4* __restrict__ T,
    float4* __restrict__ O, int n)
{
    constexpr int RPB = 256 / D4;          // rows per block
    const int r = blockIdx.x * RPB + (threadIdx.x / D4);
    const int j = threadIdx.x & (D4 - 1);
    if (r >= n) return;

    const int beg = __ldg(&rowptr[r]);
    const int end = __ldg(&rowptr[r + 1]);

    float4 aS = make_float4(0.f, 0.f, 0.f, 0.f);
    float4 aT = make_float4(0.f, 0.f, 0.f, 0.f);

    for (int i = beg; i < end; i++) {
        int2 e = __ldg(&edges[i]);
        const int   c = e.x;
        const float v = __int_as_float(e.y);
        float4 s = __ldg(&S[(size_t)c * D4 + j]);
        float4 t = __ldg(&T[(size_t)c * D4 + j]);
        aS.x = fmaf(v, s.x, aS.x); aS.y = fmaf(v, s.y, aS.y);
        aS.z = fmaf(v, s.z, aS.z); aS.w = fmaf(v, s.w, aS.w);
        aT.x = fmaf(v, t.x, aT.x); aT.y = fmaf(v, t.y, aT.y);
        aT.z = fmaf(v, t.z, aT.z); aT.w = fmaf(v, t.w, aT.w);
    }

    float4 o;
    o.x = sigmoidf_(aT.x) * aS.x;
    o.y = sigmoidf_(aT.y) * aS.y;
    o.z = sigmoidf_(aT.z) * aS.z;
    o.w = sigmoidf_(aT.w) * aS.w;
    if (RELU) {
        o.x = fmaxf(o.x, 0.f); o.y = fmaxf(o.y, 0.f);
        o.z = fmaxf(o.z, 0.f); o.w = fmaxf(o.w, 0.f);
    }
    O[(size_t)r * D4 + j] = o;
}

// ---------------------------------------------------------------------------
// Launcher (graph-capturable: async memsets + kernel launches only)
// ---------------------------------------------------------------------------
extern "C" void kernel_launch(void* const* d_in, const int* in_sizes, int n_in,
                              void* d_out, int out_size)
{
    const float* x    = (const float*)d_in[0];
    const int*   rows = (const int*)  d_in[1];
    const int*   cols = (const int*)  d_in[2];
    const float* vals = (const float*)d_in[3];
    const float* W1   = (const float*)d_in[4];
    const float* G1   = (const float*)d_in[5];
    const float* W2   = (const float*)d_in[6];
    const float* G2   = (const float*)d_in[7];
    float* out = (float*)d_out;

    float *bufA, *bufB, *h;
    int *rowptr, *cnt;
    int2 *edges;
    cudaGetSymbolAddress((void**)&bufA,   g_bufA);
    cudaGetSymbolAddress((void**)&bufB,   g_bufB);
    cudaGetSymbolAddress((void**)&h,      g_h);
    cudaGetSymbolAddress((void**)&rowptr, g_rowptr);
    cudaGetSymbolAddress((void**)&cnt,    g_cnt);
    cudaGetSymbolAddress((void**)&edges,  g_edges);

    const int M = N_NODES;
    const int EB = (E_EDGES + 255) / 256;

    // -------- CSR build (shared by both layers) --------
    cudaMemsetAsync(cnt, 0, N_NODES * sizeof(int));
    hist_kernel<<<EB, 256>>>(rows, cnt, E_EDGES);
    scan_kernel<<<1, 1024>>>(cnt, rowptr, N_NODES);
    cudaMemsetAsync(cnt, 0, N_NODES * sizeof(int));
    scatter_kernel<<<EB, 256>>>(rows, cols, vals, rowptr, cnt, edges, E_EDGES);

    // -------- Layer 1: 256 -> 256, relu --------
    {
        dim3 grid(D_HID / 128, (M + 127) / 128);
        sgemm_f32x2_kernel<<<grid, 256>>>(x, W1, bufA, M, D_IN, D_HID);
        sgemm_f32x2_kernel<<<grid, 256>>>(x, G1, bufB, M, D_IN, D_HID);
    }
    {
        int blocks = (M + 3) / 4;   // 4 rows/block at D4=64
        spmm_csr_gated_kernel<64, true><<<blocks, 256>>>(
            rowptr, edges, (const float4*)bufA, (const float4*)bufB,
            (float4*)h, M);
    }

    // -------- Layer 2: 256 -> 128 --------
    {
        dim3 grid(D_OUT / 128, (M + 127) / 128);
        sgemm_f32x2_kernel<<<grid, 256>>>(h, W2, bufA, M, D_HID, D_OUT);
        sgemm_f32x2_kernel<<<grid, 256>>>(h, G2, bufB, M, D_HID, D_OUT);
    }
    {
        int blocks = (M + 7) / 8;   // 8 rows/block at D4=32
        spmm_csr_gated_kernel<32, false><<<blocks, 256>>>(
            rowptr, edges, (const float4*)bufA, (const float4*)bufB,
            (float4*)out, M);
    }
}

// round 5
// speedup vs baseline: 2.2433x; 1.6664x over previous
#include <cuda_runtime.h>
#include <cuda_bf16.h>
#include <cstdint>

// ============================================================================
// GatedGCN on GB300 (sm_103a via compute_103 PTX -> no tcgen05; use mma.sync).
//   layer: out = sigmoid(spmm(adj, x@G)) * spmm(adj, x@W); layer1 +relu
//   - GEMMs: bf16 HMMA (mma.sync m16n8k16) with hi/lo 3-term compensation.
//   - SpMM: CSR pull (per-launch counting sort), fused gating epilogue.
// ============================================================================

#define N_NODES 50000
#define E_EDGES 800000
#define D_IN    256
#define D_HID   256
#define D_OUT   128

// ---------------------------------------------------------------------------
// Scratch (device globals: allocation-free rule)
// ---------------------------------------------------------------------------
__device__ float         g_bufA [(size_t)N_NODES * D_HID];  // support gemm out
__device__ float         g_bufB [(size_t)N_NODES * D_HID];  // gate gemm out
__device__ float         g_h    [(size_t)N_NODES * D_HID];  // hidden activation
__device__ __nv_bfloat16 g_xh  [(size_t)N_NODES * D_HID];   // act hi split
__device__ __nv_bfloat16 g_xl  [(size_t)N_NODES * D_HID];   // act lo split
__device__ __nv_bfloat16 g_w1h[D_HID * D_IN], g_w1l[D_HID * D_IN];   // Wt [N,K]
__device__ __nv_bfloat16 g_g1h[D_HID * D_IN], g_g1l[D_HID * D_IN];
__device__ __nv_bfloat16 g_w2h[D_OUT * D_HID], g_w2l[D_OUT * D_HID];
__device__ __nv_bfloat16 g_g2h[D_OUT * D_HID], g_g2l[D_OUT * D_HID];
__device__ int   g_rowptr[N_NODES + 1];
__device__ int   g_cnt   [N_NODES];
__device__ int2  g_edges [E_EDGES];

// ---------------------------------------------------------------------------
// HMMA helper: D = A(16x16 bf16) @ B(16x8 bf16) + D, fp32 accum
// ---------------------------------------------------------------------------
__device__ __forceinline__ void mma16816(float* c, const uint32_t* a,
                                         const uint32_t* b) {
    asm volatile(
        "mma.sync.aligned.m16n8k16.row.col.f32.bf16.bf16.f32 "
        "{%0,%1,%2,%3}, {%4,%5,%6,%7}, {%8,%9}, {%0,%1,%2,%3};"
        : "+f"(c[0]), "+f"(c[1]), "+f"(c[2]), "+f"(c[3])
        : "r"(a[0]), "r"(a[1]), "r"(a[2]), "r"(a[3]), "r"(b[0]), "r"(b[1]));
}

// ---------------------------------------------------------------------------
// Split / transpose-split kernels (fp32 -> bf16 hi + bf16 lo)
// ---------------------------------------------------------------------------
__global__ __launch_bounds__(256) void split_kernel(
    const float4* __restrict__ X, __nv_bfloat16* __restrict__ hi,
    __nv_bfloat16* __restrict__ lo, int n4)
{
    int i = blockIdx.x * blockDim.x + threadIdx.x;
    if (i >= n4) return;
    float4 v = X[i];
    __nv_bfloat16 h0 = __float2bfloat16_rn(v.x);
    __nv_bfloat16 h1 = __float2bfloat16_rn(v.y);
    __nv_bfloat16 h2 = __float2bfloat16_rn(v.z);
    __nv_bfloat16 h3 = __float2bfloat16_rn(v.w);
    __nv_bfloat16 l0 = __float2bfloat16_rn(v.x - __bfloat162float(h0));
    __nv_bfloat16 l1 = __float2bfloat16_rn(v.y - __bfloat162float(h1));
    __nv_bfloat16 l2 = __float2bfloat16_rn(v.z - __bfloat162float(h2));
    __nv_bfloat16 l3 = __float2bfloat16_rn(v.w - __bfloat162float(h3));
    __nv_bfloat162 hh0 = __nv_bfloat162(h0, h1), hh1 = __nv_bfloat162(h2, h3);
    __nv_bfloat162 ll0 = __nv_bfloat162(l0, l1), ll1 = __nv_bfloat162(l2, l3);
    *reinterpret_cast<uint2*>(&hi[(size_t)i * 4]) =
        make_uint2(*(uint32_t*)&hh0, *(uint32_t*)&hh1);
    *reinterpret_cast<uint2*>(&lo[(size_t)i * 4]) =
        make_uint2(*(uint32_t*)&ll0, *(uint32_t*)&ll1);
}

// W[K,N] fp32 -> out_hi/lo [N,K] bf16 (transposed, K contiguous)
__global__ __launch_bounds__(256) void tsplit_kernel(
    const float* __restrict__ W, __nv_bfloat16* __restrict__ hi,
    __nv_bfloat16* __restrict__ lo, int K, int N)
{
    int i = blockIdx.x * blockDim.x + threadIdx.x;
    if (i >= N * K) return;
    int n = i / K, k = i - n * K;
    float w = W[(size_t)k * N + n];
    __nv_bfloat16 h = __float2bfloat16_rn(w);
    hi[i] = h;
    lo[i] = __float2bfloat16_rn(w - __bfloat162float(h));
}

// ---------------------------------------------------------------------------
// HMMA GEMM with 3-term bf16 compensation, fused over {W,G}:
//   C = A @ Bt^T with A [M,K] row-major (hi/lo), Bt [NPB,K] K-major (hi/lo).
//   CTA: 128 rows x 128 cols. grid.x = 2*NPB/128: first half -> CW (weights W),
//   second half -> CG (weights G). 8 warps: warp_m = wid&1 (64 rows),
//   warp_n = wid>>1 (32 cols). Warp tile 64x32 = 4x4 m16n8 tiles.
//   K chunk 32 (2 k-steps of 16). SMEM rows padded to 40 halves: bank-exact
//   conflict-free for both A and B fragment loads.
// ---------------------------------------------------------------------------
template <int NPB>   // N per output matrix: 256 (layer1) or 128 (layer2)
__global__ __launch_bounds__(256) void gemm_mma_kernel(
    const __nv_bfloat16* __restrict__ Ah, const __nv_bfloat16* __restrict__ Al,
    const __nv_bfloat16* __restrict__ Wh, const __nv_bfloat16* __restrict__ Wl,
    const __nv_bfloat16* __restrict__ Gh, const __nv_bfloat16* __restrict__ Gl,
    float* __restrict__ CW, float* __restrict__ CG, int M)
{
    constexpr int K  = 256, KC = 32, PAD = 40;   // padded row stride (halves)
    __shared__ __nv_bfloat16 sAh[128 * PAD], sAl[128 * PAD];
    __shared__ __nv_bfloat16 sBh[128 * PAD], sBl[128 * PAD];

    const int tid  = threadIdx.x;
    const int wid  = tid >> 5;
    const int lane = tid & 31;
    const int warp_m = wid & 1;         // 0/1 -> rows [0,64) / [64,128)
    const int warp_n = wid >> 1;        // 0..3 -> cols [32*wn, 32*wn+32)
    const int row0 = blockIdx.y * 128;

    const int  nb     = NPB / 128;                  // CTA col-blocks per matrix
    const bool isW    = (int)blockIdx.x < nb;
    const int  col0   = ((int)blockIdx.x % nb) * 128;  // within selected matrix
    const __nv_bfloat16* Bh = isW ? Wh : Gh;
    const __nv_bfloat16* Bl = isW ? Wl : Gl;
    float* Cdst = isW ? CW : CG;

    float acc[4][4][4];                 // [mt][nt][4]
#pragma unroll
    for (int i = 0; i < 4; i++)
#pragma unroll
        for (int j = 0; j < 4; j++)
#pragma unroll
            for (int q = 0; q < 4; q++) acc[i][j][q] = 0.f;

    for (int k0 = 0; k0 < K; k0 += KC) {
        // ---- A tiles: 128 rows x 32 halves = 512 uint4 per precision ----
#pragma unroll
        for (int i = 0; i < 2; i++) {
            int idx = tid + i * 256;            // 0..511
            int r = idx >> 2, v = idx & 3;      // row, vec4-of-8-halves
            int grow = row0 + r;
            uint4 vh = make_uint4(0, 0, 0, 0), vl = vh;
            if (grow < M) {
                vh = *reinterpret_cast<const uint4*>(&Ah[(size_t)grow * K + k0 + v * 8]);
                vl = *reinterpret_cast<const uint4*>(&Al[(size_t)grow * K + k0 + v * 8]);
            }
            *reinterpret_cast<uint4*>(&sAh[r * PAD + v * 8]) = vh;
            *reinterpret_cast<uint4*>(&sAl[r * PAD + v * 8]) = vl;
        }
        // ---- B tiles: 128 n-rows x 32 halves ----
#pragma unroll
        for (int i = 0; i < 2; i++) {
            int idx = tid + i * 256;
            int r = idx >> 2, v = idx & 3;
            uint4 vh = *reinterpret_cast<const uint4*>(
                &Bh[(size_t)(col0 + r) * K + k0 + v * 8]);
            uint4 vl = *reinterpret_cast<const uint4*>(
                &Bl[(size_t)(col0 + r) * K + k0 + v * 8]);
            *reinterpret_cast<uint4*>(&sBh[r * PAD + v * 8]) = vh;
            *reinterpret_cast<uint4*>(&sBl[r * PAD + v * 8]) = vl;
        }
        __syncthreads();

#pragma unroll
        for (int ks = 0; ks < KC / 16; ks++) {
            const int kk = ks * 16 + (lane & 3) * 2;
            // B fragments for all 4 n-tiles (hi & lo)
            uint32_t bh[4][2], bl[4][2];
#pragma unroll
            for (int nt = 0; nt < 4; nt++) {
                int n = warp_n * 32 + nt * 8 + (lane >> 2);
                bh[nt][0] = *(const uint32_t*)&sBh[n * PAD + kk];
                bh[nt][1] = *(const uint32_t*)&sBh[n * PAD + kk + 8];
                bl[nt][0] = *(const uint32_t*)&sBl[n * PAD + kk];
                bl[nt][1] = *(const uint32_t*)&sBl[n * PAD + kk + 8];
            }
#pragma unroll
            for (int mt = 0; mt < 4; mt++) {
                int r = warp_m * 64 + mt * 16 + (lane >> 2);
                uint32_t ah[4], al[4];
                ah[0] = *(const uint32_t*)&sAh[r * PAD + kk];
                ah[1] = *(const uint32_t*)&sAh[(r + 8) * PAD + kk];
                ah[2] = *(const uint32_t*)&sAh[r * PAD + kk + 8];
                ah[3] = *(const uint32_t*)&sAh[(r + 8) * PAD + kk + 8];
                al[0] = *(const uint32_t*)&sAl[r * PAD + kk];
                al[1] = *(const uint32_t*)&sAl[(r + 8) * PAD + kk];
                al[2] = *(const uint32_t*)&sAl[r * PAD + kk + 8];
                al[3] = *(const uint32_t*)&sAl[(r + 8) * PAD + kk + 8];
#pragma unroll
                for (int nt = 0; nt < 4; nt++) {
                    mma16816(acc[mt][nt], ah, bh[nt]);   // Ah*Bh
                    mma16816(acc[mt][nt], ah, bl[nt]);   // Ah*Bl
                    mma16816(acc[mt][nt], al, bh[nt]);   // Al*Bh
                }
            }
        }
        __syncthreads();
    }

    // ---- epilogue ----
#pragma unroll
    for (int mt = 0; mt < 4; mt++) {
        int r_lo = row0 + warp_m * 64 + mt * 16 + (lane >> 2);
#pragma unroll
        for (int nt = 0; nt < 4; nt++) {
            int n = col0 + warp_n * 32 + nt * 8 + (lane & 3) * 2;
            if (r_lo < M)
                *reinterpret_cast<float2*>(&Cdst[(size_t)r_lo * NPB + n]) =
                    make_float2(acc[mt][nt][0], acc[mt][nt][1]);
            if (r_lo + 8 < M)
                *reinterpret_cast<float2*>(&Cdst[(size_t)(r_lo + 8) * NPB + n]) =
                    make_float2(acc[mt][nt][2], acc[mt][nt][3]);
        }
    }
}

// ---------------------------------------------------------------------------
// CSR build: histogram -> scan -> scatter
// ---------------------------------------------------------------------------
__global__ __launch_bounds__(256) void hist_kernel(
    const int* __restrict__ rows, int* __restrict__ cnt, int E)
{
    int e = blockIdx.x * blockDim.x + threadIdx.x;
    if (e < E) atomicAdd(&cnt[rows[e]], 1);
}

__global__ __launch_bounds__(1024) void scan_kernel(
    const int* __restrict__ cnt, int* __restrict__ rowptr, int n)
{
    __shared__ int warp_sums[32];
    __shared__ int s_carry;
    const int tid = threadIdx.x;
    const int lane = tid & 31, w = tid >> 5;
    if (tid == 0) { rowptr[0] = 0; s_carry = 0; }
    __syncthreads();

    for (int base = 0; base < n; base += 1024) {
        int i = base + tid;
        int v = (i < n) ? cnt[i] : 0;
        int s = v;
#pragma unroll
        for (int o = 1; o < 32; o <<= 1) {
            int t = __shfl_up_sync(0xffffffffu, s, o);
            if (lane >= o) s += t;
        }
        if (lane == 31) warp_sums[w] = s;
        __syncthreads();
        if (w == 0) {
            int ws = warp_sums[lane];
#pragma unroll
            for (int o = 1; o < 32; o <<= 1) {
                int t = __shfl_up_sync(0xffffffffu, ws, o);
                if (lane >= o) ws += t;
            }
            warp_sums[lane] = ws;
        }
        __syncthreads();
        int incl = s + (w > 0 ? warp_sums[w - 1] : 0) + s_carry;
        if (i < n) rowptr[i + 1] = incl;
        __syncthreads();
        if (tid == 1023) s_carry = incl;
        __syncthreads();
    }
}

__global__ __launch_bounds__(256) void scatter_kernel(
    const int* __restrict__ rows, const int* __restrict__ cols,
    const float* __restrict__ vals,
    const int* __restrict__ rowptr, int* __restrict__ cursor,
    int2* __restrict__ edges, int E)
{
    int e = blockIdx.x * blockDim.x + threadIdx.x;
    if (e >= E) return;
    int r = rows[e];
    int pos = rowptr[r] + atomicAdd(&cursor[r], 1);
    edges[pos] = make_int2(cols[e], __float_as_int(vals[e]));
}

// ---------------------------------------------------------------------------
// Fused CSR dual-SpMM + gating epilogue (pull, no atomics)
// ---------------------------------------------------------------------------
__device__ __forceinline__ float sigmoidf_(float x) {
    return 1.f / (1.f + expf(-x));
}

template <int D4, bool RELU>
__global__ __launch_bounds__(256) void spmm_csr_gated_kernel(
    const int*  __restrict__ rowptr, const int2* __restrict__ edges,
    const float4* __restrict__ S, const float4* __restrict__ T,
    float4* __restrict__ O, int n)
{
    constexpr int RPB = 256 / D4;
    const int r = blockIdx.x * RPB + (threadIdx.x / D4);
    const int j = threadIdx.x & (D4 - 1);
    if (r >= n) return;

    const int beg = __ldg(&rowptr[r]);
    const int end = __ldg(&rowptr[r + 1]);

    float4 aS = make_float4(0.f, 0.f, 0.f, 0.f);
    float4 aT = make_float4(0.f, 0.f, 0.f, 0.f);

    for (int i = beg; i < end; i++) {
        int2 e = __ldg(&edges[i]);
        const int   c = e.x;
        const float v = __int_as_float(e.y);
        float4 s = __ldg(&S[(size_t)c * D4 + j]);
        float4 t = __ldg(&T[(size_t)c * D4 + j]);
        aS.x = fmaf(v, s.x, aS.x); aS.y = fmaf(v, s.y, aS.y);
        aS.z = fmaf(v, s.z, aS.z); aS.w = fmaf(v, s.w, aS.w);
        aT.x = fmaf(v, t.x, aT.x); aT.y = fmaf(v, t.y, aT.y);
        aT.z = fmaf(v, t.z, aT.z); aT.w = fmaf(v, t.w, aT.w);
    }

    float4 o;
    o.x = sigmoidf_(aT.x) * aS.x;
    o.y = sigmoidf_(aT.y) * aS.y;
    o.z = sigmoidf_(aT.z) * aS.z;
    o.w = sigmoidf_(aT.w) * aS.w;
    if (RELU) {
        o.x = fmaxf(o.x, 0.f); o.y = fmaxf(o.y, 0.f);
        o.z = fmaxf(o.z, 0.f); o.w = fmaxf(o.w, 0.f);
    }
    O[(size_t)r * D4 + j] = o;
}

// ---------------------------------------------------------------------------
// Launcher (graph-capturable)
// ---------------------------------------------------------------------------
extern "C" void kernel_launch(void* const* d_in, const int* in_sizes, int n_in,
                              void* d_out, int out_size)
{
    const float* x    = (const float*)d_in[0];
    const int*   rows = (const int*)  d_in[1];
    const int*   cols = (const int*)  d_in[2];
    const float* vals = (const float*)d_in[3];
    const float* W1   = (const float*)d_in[4];
    const float* G1   = (const float*)d_in[5];
    const float* W2   = (const float*)d_in[6];
    const float* G2   = (const float*)d_in[7];
    float* out = (float*)d_out;

    float *bufA, *bufB, *h;
    __nv_bfloat16 *xh, *xl, *w1h, *w1l, *g1h, *g1l, *w2h, *w2l, *g2h, *g2l;
    int *rowptr, *cnt;
    int2 *edges;
    cudaGetSymbolAddress((void**)&bufA,   g_bufA);
    cudaGetSymbolAddress((void**)&bufB,   g_bufB);
    cudaGetSymbolAddress((void**)&h,      g_h);
    cudaGetSymbolAddress((void**)&xh,     g_xh);
    cudaGetSymbolAddress((void**)&xl,     g_xl);
    cudaGetSymbolAddress((void**)&w1h,    g_w1h);
    cudaGetSymbolAddress((void**)&w1l,    g_w1l);
    cudaGetSymbolAddress((void**)&g1h,    g_g1h);
    cudaGetSymbolAddress((void**)&g1l,    g_g1l);
    cudaGetSymbolAddress((void**)&w2h,    g_w2h);
    cudaGetSymbolAddress((void**)&w2l,    g_w2l);
    cudaGetSymbolAddress((void**)&g2h,    g_g2h);
    cudaGetSymbolAddress((void**)&g2l,    g_g2l);
    cudaGetSymbolAddress((void**)&rowptr, g_rowptr);
    cudaGetSymbolAddress((void**)&cnt,    g_cnt);
    cudaGetSymbolAddress((void**)&edges,  g_edges);

    const int M  = N_NODES;
    const int EB = (E_EDGES + 255) / 256;
    const int MT = (M + 127) / 128;                 // 391 M-tiles

    // -------- CSR build --------
    cudaMemsetAsync(cnt, 0, N_NODES * sizeof(int));
    hist_kernel<<<EB, 256>>>(rows, cnt, E_EDGES);
    scan_kernel<<<1, 1024>>>(cnt, rowptr, N_NODES);
    cudaMemsetAsync(cnt, 0, N_NODES * sizeof(int));
    scatter_kernel<<<EB, 256>>>(rows, cols, vals, rowptr, cnt, edges, E_EDGES);

    // -------- operand prep --------
    {
        int n4 = M * D_IN / 4;
        split_kernel<<<(n4 + 255) / 256, 256>>>((const float4*)x, xh, xl, n4);
        int nw1 = D_HID * D_IN;
        tsplit_kernel<<<(nw1 + 255) / 256, 256>>>(W1, w1h, w1l, D_IN, D_HID);
        tsplit_kernel<<<(nw1 + 255) / 256, 256>>>(G1, g1h, g1l, D_IN, D_HID);
        int nw2 = D_OUT * D_HID;
        tsplit_kernel<<<(nw2 + 255) / 256, 256>>>(W2, w2h, w2l, D_HID, D_OUT);
        tsplit_kernel<<<(nw2 + 255) / 256, 256>>>(G2, g2h, g2l, D_HID, D_OUT);
    }

    // -------- Layer 1: 256 -> 256, relu --------
    gemm_mma_kernel<256><<<dim3(4, MT), 256>>>(xh, xl, w1h, w1l, g1h, g1l,
                                               bufA, bufB, M);
    spmm_csr_gated_kernel<64, true><<<(M + 3) / 4, 256>>>(
        rowptr, edges, (const float4*)bufA, (const float4*)bufB, (float4*)h, M);

    // -------- Layer 2: 256 -> 128 --------
    {
        int n4 = M * D_HID / 4;
        split_kernel<<<(n4 + 255) / 256, 256>>>((const float4*)h, xh, xl, n4);
    }
    gemm_mma_kernel<128><<<dim3(2, MT), 256>>>(xh, xl, w2h, w2l, g2h, g2l,
                                               bufA, bufB, M);
    spmm_csr_gated_kernel<32, false><<<(M + 7) / 8, 256>>>(
        rowptr, edges, (const float4*)bufA, (const float4*)bufB, (float4*)out, M);
}

// round 6
// speedup vs baseline: 2.6924x; 1.2002x over previous
#include <cuda_runtime.h>
#include <cuda_bf16.h>
#include <cstdint>

// ============================================================================
// GatedGCN on GB300 (compute_103 PTX -> mma.sync HMMA path).
// KEY IDENTITY: spmm(adj, x@W) = spmm(adj, x)@W  (spmm is linear)
//   per layer: Z = spmm(adj, X); out = act(sigmoid(Z@G) * (Z@W))
//   - ONE single-matrix CSR pull-SpMM per layer (epilogue emits bf16 hi/lo)
//   - ONE fused dual-GEMM per layer (HMMA bf16 3-term comp, gating epilogue)
// ============================================================================

#define N_NODES 50000
#define E_EDGES 800000
#define D_IN    256
#define D_HID   256
#define D_OUT   128

// ---------------------------------------------------------------------------
// Scratch (device globals: allocation-free rule)
// ---------------------------------------------------------------------------
__device__ __nv_bfloat16 g_Zh [(size_t)N_NODES * 256];   // spmm out hi
__device__ __nv_bfloat16 g_Zl [(size_t)N_NODES * 256];   // spmm out lo
__device__ float         g_h  [(size_t)N_NODES * D_HID]; // hidden activation
__device__ __nv_bfloat16 g_w1h[D_HID * D_IN], g_w1l[D_HID * D_IN];   // Wt [N,K]
__device__ __nv_bfloat16 g_g1h[D_HID * D_IN], g_g1l[D_HID * D_IN];
__device__ __nv_bfloat16 g_w2h[D_OUT * D_HID], g_w2l[D_OUT * D_HID];
__device__ __nv_bfloat16 g_g2h[D_OUT * D_HID], g_g2l[D_OUT * D_HID];
__device__ int   g_rowptr[N_NODES + 1];
__device__ int   g_cnt   [N_NODES];
__device__ int2  g_edges [E_EDGES];

// ---------------------------------------------------------------------------
// HMMA helper: D = A(16x16 bf16) @ B(16x8 bf16) + D, fp32 accum
// ---------------------------------------------------------------------------
__device__ __forceinline__ void mma16816(float* c, const uint32_t* a,
                                         const uint32_t* b) {
    asm volatile(
        "mma.sync.aligned.m16n8k16.row.col.f32.bf16.bf16.f32 "
        "{%0,%1,%2,%3}, {%4,%5,%6,%7}, {%8,%9}, {%0,%1,%2,%3};"
        : "+f"(c[0]), "+f"(c[1]), "+f"(c[2]), "+f"(c[3])
        : "r"(a[0]), "r"(a[1]), "r"(a[2]), "r"(a[3]), "r"(b[0]), "r"(b[1]));
}

__device__ __forceinline__ float sigmoidf_(float x) {
    return 1.f / (1.f + expf(-x));
}

// ---------------------------------------------------------------------------
// Weight transpose+split: W[K,N] fp32 -> hi/lo [N,K] bf16 (K contiguous)
// ---------------------------------------------------------------------------
__global__ __launch_bounds__(256) void tsplit_kernel(
    const float* __restrict__ W, __nv_bfloat16* __restrict__ hi,
    __nv_bfloat16* __restrict__ lo, int K, int N)
{
    int i = blockIdx.x * blockDim.x + threadIdx.x;
    if (i >= N * K) return;
    int n = i / K, k = i - n * K;
    float w = W[(size_t)k * N + n];
    __nv_bfloat16 h = __float2bfloat16_rn(w);
    hi[i] = h;
    lo[i] = __float2bfloat16_rn(w - __bfloat162float(h));
}

// ---------------------------------------------------------------------------
// CSR build: histogram -> scan -> scatter
// ---------------------------------------------------------------------------
__global__ __launch_bounds__(256) void hist_kernel(
    const int* __restrict__ rows, int* __restrict__ cnt, int E)
{
    int e = blockIdx.x * blockDim.x + threadIdx.x;
    if (e < E) atomicAdd(&cnt[rows[e]], 1);
}

__global__ __launch_bounds__(1024) void scan_kernel(
    const int* __restrict__ cnt, int* __restrict__ rowptr, int n)
{
    __shared__ int warp_sums[32];
    __shared__ int s_carry;
    const int tid = threadIdx.x;
    const int lane = tid & 31, w = tid >> 5;
    if (tid == 0) { rowptr[0] = 0; s_carry = 0; }
    __syncthreads();

    for (int base = 0; base < n; base += 1024) {
        int i = base + tid;
        int v = (i < n) ? cnt[i] : 0;
        int s = v;
#pragma unroll
        for (int o = 1; o < 32; o <<= 1) {
            int t = __shfl_up_sync(0xffffffffu, s, o);
            if (lane >= o) s += t;
        }
        if (lane == 31) warp_sums[w] = s;
        __syncthreads();
        if (w == 0) {
            int ws = warp_sums[lane];
#pragma unroll
            for (int o = 1; o < 32; o <<= 1) {
                int t = __shfl_up_sync(0xffffffffu, ws, o);
                if (lane >= o) ws += t;
            }
            warp_sums[lane] = ws;
        }
        __syncthreads();
        int incl = s + (w > 0 ? warp_sums[w - 1] : 0) + s_carry;
        if (i < n) rowptr[i + 1] = incl;
        __syncthreads();
        if (tid == 1023) s_carry = incl;
        __syncthreads();
    }
}

__global__ __launch_bounds__(256) void scatter_kernel(
    const int* __restrict__ rows, const int* __restrict__ cols,
    const float* __restrict__ vals,
    const int* __restrict__ rowptr, int* __restrict__ cursor,
    int2* __restrict__ edges, int E)
{
    int e = blockIdx.x * blockDim.x + threadIdx.x;
    if (e >= E) return;
    int r = rows[e];
    int pos = rowptr[r] + atomicAdd(&cursor[r], 1);
    edges[pos] = make_int2(cols[e], __float_as_int(vals[e]));
}

// ---------------------------------------------------------------------------
// Single-matrix CSR pull-SpMM, epilogue splits fp32 accum -> bf16 hi/lo.
//   Z[r] = sum_e v_e * X[c_e]; D = 256 (64 float4 per row, 64 thr/row)
// ---------------------------------------------------------------------------
__global__ __launch_bounds__(256) void spmm_split_kernel(
    const int*  __restrict__ rowptr, const int2* __restrict__ edges,
    const float4* __restrict__ X,
    __nv_bfloat16* __restrict__ Zh, __nv_bfloat16* __restrict__ Zl, int n)
{
    constexpr int D4 = 64;                 // float4 chunks per row
    const int r = blockIdx.x * 4 + (threadIdx.x >> 6);
    const int j = threadIdx.x & 63;
    if (r >= n) return;

    const int beg = __ldg(&rowptr[r]);
    const int end = __ldg(&rowptr[r + 1]);

    float4 a = make_float4(0.f, 0.f, 0.f, 0.f);
    for (int i = beg; i < end; i++) {
        int2 e = __ldg(&edges[i]);
        const float v = __int_as_float(e.y);
        float4 s = __ldg(&X[(size_t)e.x * D4 + j]);
        a.x = fmaf(v, s.x, a.x); a.y = fmaf(v, s.y, a.y);
        a.z = fmaf(v, s.z, a.z); a.w = fmaf(v, s.w, a.w);
    }

    __nv_bfloat16 h0 = __float2bfloat16_rn(a.x);
    __nv_bfloat16 h1 = __float2bfloat16_rn(a.y);
    __nv_bfloat16 h2 = __float2bfloat16_rn(a.z);
    __nv_bfloat16 h3 = __float2bfloat16_rn(a.w);
    __nv_bfloat16 l0 = __float2bfloat16_rn(a.x - __bfloat162float(h0));
    __nv_bfloat16 l1 = __float2bfloat16_rn(a.y - __bfloat162float(h1));
    __nv_bfloat16 l2 = __float2bfloat16_rn(a.z - __bfloat162float(h2));
    __nv_bfloat16 l3 = __float2bfloat16_rn(a.w - __bfloat162float(h3));
    __nv_bfloat162 hh0 = __nv_bfloat162(h0, h1), hh1 = __nv_bfloat162(h2, h3);
    __nv_bfloat162 ll0 = __nv_bfloat162(l0, l1), ll1 = __nv_bfloat162(l2, l3);
    size_t o = (size_t)r * 256 + j * 4;
    *reinterpret_cast<uint2*>(&Zh[o]) = make_uint2(*(uint32_t*)&hh0, *(uint32_t*)&hh1);
    *reinterpret_cast<uint2*>(&Zl[o]) = make_uint2(*(uint32_t*)&ll0, *(uint32_t*)&ll1);
}

// ---------------------------------------------------------------------------
// Fused gated dual-GEMM:  O = act( sigmoid(Z@G) * (Z@W) )
//   Z: [M,256] bf16 hi/lo row-major. W/G: [NOUT,256] bf16 hi/lo K-major.
//   CTA: 128 rows x 64 cols (of BOTH W and G). grid.x = NOUT/64.
//   8 warps: warp_m = wid&3 (32 rows), warp_n = wid>>2 (32 cols).
//   Warp tile 32x32 per output = 2x4 m16n8 tiles; 3-term compensation.
//   PAD=40 halves keeps both A and B fragment LDS conflict-free.
// ---------------------------------------------------------------------------
template <int NOUT, bool RELU>
__global__ __launch_bounds__(256) void gemm_gated_kernel(
    const __nv_bfloat16* __restrict__ Ah, const __nv_bfloat16* __restrict__ Al,
    const __nv_bfloat16* __restrict__ Wh, const __nv_bfloat16* __restrict__ Wl,
    const __nv_bfloat16* __restrict__ Gh, const __nv_bfloat16* __restrict__ Gl,
    float* __restrict__ O, int M)
{
    constexpr int K = 256, KC = 32, PAD = 40;
    __shared__ __nv_bfloat16 sAh[128 * PAD], sAl[128 * PAD];
    __shared__ __nv_bfloat16 sWh[64 * PAD],  sWl[64 * PAD];
    __shared__ __nv_bfloat16 sGh[64 * PAD],  sGl[64 * PAD];

    const int tid  = threadIdx.x;
    const int wid  = tid >> 5;
    const int lane = tid & 31;
    const int warp_m = wid & 3;        // 4 groups of 32 rows
    const int warp_n = wid >> 2;       // 2 groups of 32 cols
    const int row0 = blockIdx.y * 128;
    const int col0 = blockIdx.x * 64;

    float accS[2][4][4], accT[2][4][4];
#pragma unroll
    for (int i = 0; i < 2; i++)
#pragma unroll
        for (int j = 0; j < 4; j++)
#pragma unroll
            for (int q = 0; q < 4; q++) { accS[i][j][q] = 0.f; accT[i][j][q] = 0.f; }

    for (int k0 = 0; k0 < K; k0 += KC) {
        // ---- A tiles: 128 rows x 32 halves, hi+lo: 512 uint4 each ----
#pragma unroll
        for (int i = 0; i < 2; i++) {
            int idx = tid + i * 256;
            int r = idx >> 2, v = idx & 3;
            int grow = row0 + r;
            uint4 vh = make_uint4(0, 0, 0, 0), vl = vh;
            if (grow < M) {
                vh = *reinterpret_cast<const uint4*>(&Ah[(size_t)grow * K + k0 + v * 8]);
                vl = *reinterpret_cast<const uint4*>(&Al[(size_t)grow * K + k0 + v * 8]);
            }
            *reinterpret_cast<uint4*>(&sAh[r * PAD + v * 8]) = vh;
            *reinterpret_cast<uint4*>(&sAl[r * PAD + v * 8]) = vl;
        }
        // ---- B tiles: 64 n-rows x 32 halves x {Wh,Wl,Gh,Gl}: 256 uint4 each
        {
            int r = tid >> 2, v = tid & 3;      // 256 threads cover one matrix
            size_t go = (size_t)(col0 + r) * K + k0 + v * 8;
            *reinterpret_cast<uint4*>(&sWh[r * PAD + v * 8]) =
                *reinterpret_cast<const uint4*>(&Wh[go]);
            *reinterpret_cast<uint4*>(&sWl[r * PAD + v * 8]) =
                *reinterpret_cast<const uint4*>(&Wl[go]);
            *reinterpret_cast<uint4*>(&sGh[r * PAD + v * 8]) =
                *reinterpret_cast<const uint4*>(&Gh[go]);
            *reinterpret_cast<uint4*>(&sGl[r * PAD + v * 8]) =
                *reinterpret_cast<const uint4*>(&Gl[go]);
        }
        __syncthreads();

#pragma unroll
        for (int ks = 0; ks < KC / 16; ks++) {
            const int kk = ks * 16 + (lane & 3) * 2;
            uint32_t wh[4][2], wl[4][2], gh[4][2], gl[4][2];
#pragma unroll
            for (int nt = 0; nt < 4; nt++) {
                int n = warp_n * 32 + nt * 8 + (lane >> 2);
                wh[nt][0] = *(const uint32_t*)&sWh[n * PAD + kk];
                wh[nt][1] = *(const uint32_t*)&sWh[n * PAD + kk + 8];
                wl[nt][0] = *(const uint32_t*)&sWl[n * PAD + kk];
                wl[nt][1] = *(const uint32_t*)&sWl[n * PAD + kk + 8];
                gh[nt][0] = *(const uint32_t*)&sGh[n * PAD + kk];
                gh[nt][1] = *(const uint32_t*)&sGh[n * PAD + kk + 8];
                gl[nt][0] = *(const uint32_t*)&sGl[n * PAD + kk];
                gl[nt][1] = *(const uint32_t*)&sGl[n * PAD + kk + 8];
            }
#pragma unroll
            for (int mt = 0; mt < 2; mt++) {
                int r = warp_m * 32 + mt * 16 + (lane >> 2);
                uint32_t ah[4], al[4];
                ah[0] = *(const uint32_t*)&sAh[r * PAD + kk];
                ah[1] = *(const uint32_t*)&sAh[(r + 8) * PAD + kk];
                ah[2] = *(const uint32_t*)&sAh[r * PAD + kk + 8];
                ah[3] = *(const uint32_t*)&sAh[(r + 8) * PAD + kk + 8];
                al[0] = *(const uint32_t*)&sAl[r * PAD + kk];
                al[1] = *(const uint32_t*)&sAl[(r + 8) * PAD + kk];
                al[2] = *(const uint32_t*)&sAl[r * PAD + kk + 8];
                al[3] = *(const uint32_t*)&sAl[(r + 8) * PAD + kk + 8];
#pragma unroll
                for (int nt = 0; nt < 4; nt++) {
                    mma16816(accS[mt][nt], ah, wh[nt]);
                    mma16816(accS[mt][nt], ah, wl[nt]);
                    mma16816(accS[mt][nt], al, wh[nt]);
                    mma16816(accT[mt][nt], ah, gh[nt]);
                    mma16816(accT[mt][nt], ah, gl[nt]);
                    mma16816(accT[mt][nt], al, gh[nt]);
                }
            }
        }
        __syncthreads();
    }

    // ---- gated epilogue: o = act(sigmoid(T) * S) ----
#pragma unroll
    for (int mt = 0; mt < 2; mt++) {
        int r_lo = row0 + warp_m * 32 + mt * 16 + (lane >> 2);
#pragma unroll
        for (int nt = 0; nt < 4; nt++) {
            int n = col0 + warp_n * 32 + nt * 8 + (lane & 3) * 2;
            float o0 = sigmoidf_(accT[mt][nt][0]) * accS[mt][nt][0];
            float o1 = sigmoidf_(accT[mt][nt][1]) * accS[mt][nt][1];
            float o2 = sigmoidf_(accT[mt][nt][2]) * accS[mt][nt][2];
            float o3 = sigmoidf_(accT[mt][nt][3]) * accS[mt][nt][3];
            if (RELU) {
                o0 = fmaxf(o0, 0.f); o1 = fmaxf(o1, 0.f);
                o2 = fmaxf(o2, 0.f); o3 = fmaxf(o3, 0.f);
            }
            if (r_lo < M)
                *reinterpret_cast<float2*>(&O[(size_t)r_lo * NOUT + n]) =
                    make_float2(o0, o1);
            if (r_lo + 8 < M)
                *reinterpret_cast<float2*>(&O[(size_t)(r_lo + 8) * NOUT + n]) =
                    make_float2(o2, o3);
        }
    }
}

// ---------------------------------------------------------------------------
// Launcher (graph-capturable)
// ---------------------------------------------------------------------------
extern "C" void kernel_launch(void* const* d_in, const int* in_sizes, int n_in,
                              void* d_out, int out_size)
{
    const float* x    = (const float*)d_in[0];
    const int*   rows = (const int*)  d_in[1];
    const int*   cols = (const int*)  d_in[2];
    const float* vals = (const float*)d_in[3];
    const float* W1   = (const float*)d_in[4];
    const float* G1   = (const float*)d_in[5];
    const float* W2   = (const float*)d_in[6];
    const float* G2   = (const float*)d_in[7];
    float* out = (float*)d_out;

    __nv_bfloat16 *Zh, *Zl, *w1h, *w1l, *g1h, *g1l, *w2h, *w2l, *g2h, *g2l;
    float* h;
    int *rowptr, *cnt;
    int2 *edges;
    cudaGetSymbolAddress((void**)&Zh,     g_Zh);
    cudaGetSymbolAddress((void**)&Zl,     g_Zl);
    cudaGetSymbolAddress((void**)&h,      g_h);
    cudaGetSymbolAddress((void**)&w1h,    g_w1h);
    cudaGetSymbolAddress((void**)&w1l,    g_w1l);
    cudaGetSymbolAddress((void**)&g1h,    g_g1h);
    cudaGetSymbolAddress((void**)&g1l,    g_g1l);
    cudaGetSymbolAddress((void**)&w2h,    g_w2h);
    cudaGetSymbolAddress((void**)&w2l,    g_w2l);
    cudaGetSymbolAddress((void**)&g2h,    g_g2h);
    cudaGetSymbolAddress((void**)&g2l,    g_g2l);
    cudaGetSymbolAddress((void**)&rowptr, g_rowptr);
    cudaGetSymbolAddress((void**)&cnt,    g_cnt);
    cudaGetSymbolAddress((void**)&edges,  g_edges);

    const int M  = N_NODES;
    const int EB = (E_EDGES + 255) / 256;
    const int MT = (M + 127) / 128;                 // 391 M-tiles

    // -------- CSR build --------
    cudaMemsetAsync(cnt, 0, N_NODES * sizeof(int));
    hist_kernel<<<EB, 256>>>(rows, cnt, E_EDGES);
    scan_kernel<<<1, 1024>>>(cnt, rowptr, N_NODES);
    cudaMemsetAsync(cnt, 0, N_NODES * sizeof(int));
    scatter_kernel<<<EB, 256>>>(rows, cols, vals, rowptr, cnt, edges, E_EDGES);

    // -------- weight prep --------
    {
        int nw1 = D_HID * D_IN;
        tsplit_kernel<<<(nw1 + 255) / 256, 256>>>(W1, w1h, w1l, D_IN, D_HID);
        tsplit_kernel<<<(nw1 + 255) / 256, 256>>>(G1, g1h, g1l, D_IN, D_HID);
        int nw2 = D_OUT * D_HID;
        tsplit_kernel<<<(nw2 + 255) / 256, 256>>>(W2, w2h, w2l, D_HID, D_OUT);
        tsplit_kernel<<<(nw2 + 255) / 256, 256>>>(G2, g2h, g2l, D_HID, D_OUT);
    }

    // -------- Layer 1: Z = spmm(adj, x); h = relu(sig(Z@G1)*(Z@W1)) --------
    spmm_split_kernel<<<(M + 3) / 4, 256>>>(rowptr, edges, (const float4*)x,
                                            Zh, Zl, M);
    gemm_gated_kernel<D_HID, true><<<dim3(D_HID / 64, MT), 256>>>(
        Zh, Zl, w1h, w1l, g1h, g1l, h, M);

    // -------- Layer 2: Z = spmm(adj, h); out = sig(Z@G2)*(Z@W2) --------
    spmm_split_kernel<<<(M + 3) / 4, 256>>>(rowptr, edges, (const float4*)h,
                                            Zh, Zl, M);
    gemm_gated_kernel<D_OUT, false><<<dim3(D_OUT / 64, MT), 256>>>(
        Zh, Zl, w2h, w2l, g2h, g2l, out, M);
}

// round 7
// speedup vs baseline: 2.9638x; 1.1008x over previous
#include <cuda_runtime.h>
#include <cuda_bf16.h>
#include <cstdint>

// ============================================================================
// GatedGCN on GB300 (compute_103 PTX -> mma.sync HMMA + cp.async + ldmatrix).
// Identity: spmm(adj, x@W) = spmm(adj, x)@W
//   per layer: Z = spmm(adj, X); out = act(sigmoid(Z@G) * (Z@W))
//   - single-matrix CSR pull-SpMM (epilogue emits bf16 hi/lo)
//   - fused gated dual-GEMM: bf16 3-term compensation, cp.async double-buffer,
//     ldmatrix fragment loads, gating epilogue in-register.
// ============================================================================

#define N_NODES 50000
#define E_EDGES 800000
#define D_IN    256
#define D_HID   256
#define D_OUT   128

// ---------------------------------------------------------------------------
// Scratch (device globals: allocation-free rule)
// ---------------------------------------------------------------------------
__device__ __nv_bfloat16 g_Zh [(size_t)N_NODES * 256];   // spmm out hi
__device__ __nv_bfloat16 g_Zl [(size_t)N_NODES * 256];   // spmm out lo
__device__ float         g_h  [(size_t)N_NODES * D_HID]; // hidden activation
__device__ __nv_bfloat16 g_w1h[D_HID * D_IN], g_w1l[D_HID * D_IN];   // Wt [N,K]
__device__ __nv_bfloat16 g_g1h[D_HID * D_IN], g_g1l[D_HID * D_IN];
__device__ __nv_bfloat16 g_w2h[D_OUT * D_HID], g_w2l[D_OUT * D_HID];
__device__ __nv_bfloat16 g_g2h[D_OUT * D_HID], g_g2l[D_OUT * D_HID];
__device__ int   g_rowptr[N_NODES + 1];
__device__ int   g_cnt   [N_NODES];
__device__ int2  g_edges [E_EDGES];

// ---------------------------------------------------------------------------
// PTX helpers
// ---------------------------------------------------------------------------
__device__ __forceinline__ void mma16816(float* c, const uint32_t* a,
                                         const uint32_t* b) {
    asm volatile(
        "mma.sync.aligned.m16n8k16.row.col.f32.bf16.bf16.f32 "
        "{%0,%1,%2,%3}, {%4,%5,%6,%7}, {%8,%9}, {%0,%1,%2,%3};"
        : "+f"(c[0]), "+f"(c[1]), "+f"(c[2]), "+f"(c[3])
        : "r"(a[0]), "r"(a[1]), "r"(a[2]), "r"(a[3]), "r"(b[0]), "r"(b[1]));
}
__device__ __forceinline__ void ldmx4(uint32_t* r, uint32_t addr) {
    asm volatile("ldmatrix.sync.aligned.m8n8.x4.shared.b16 {%0,%1,%2,%3}, [%4];"
                 : "=r"(r[0]), "=r"(r[1]), "=r"(r[2]), "=r"(r[3]) : "r"(addr));
}
__device__ __forceinline__ void ldmx2(uint32_t* r, uint32_t addr) {
    asm volatile("ldmatrix.sync.aligned.m8n8.x2.shared.b16 {%0,%1}, [%2];"
                 : "=r"(r[0]), "=r"(r[1]) : "r"(addr));
}
__device__ __forceinline__ void cpasync16(uint32_t sdst, const void* gsrc,
                                          uint32_t sz) {
    asm volatile("cp.async.cg.shared.global [%0], [%1], 16, %2;"
                 :: "r"(sdst), "l"(gsrc), "r"(sz));
}
__device__ __forceinline__ void cpcommit() {
    asm volatile("cp.async.commit_group;");
}
template <int N>
__device__ __forceinline__ void cpwait() {
    asm volatile("cp.async.wait_group %0;" :: "n"(N));
}
__device__ __forceinline__ float sigmoidf_(float x) {
    return 1.f / (1.f + expf(-x));
}

// ---------------------------------------------------------------------------
// All-weights transpose+split in ONE launch:
//   W1,G1: [256,256] -> [256,256]^T ; W2,G2: [256,128] -> [128,256]^T
// ---------------------------------------------------------------------------
__global__ __launch_bounds__(256) void wsplit_all_kernel(
    const float* __restrict__ W1, const float* __restrict__ G1,
    const float* __restrict__ W2, const float* __restrict__ G2,
    __nv_bfloat16* __restrict__ w1h, __nv_bfloat16* __restrict__ w1l,
    __nv_bfloat16* __restrict__ g1h, __nv_bfloat16* __restrict__ g1l,
    __nv_bfloat16* __restrict__ w2h, __nv_bfloat16* __restrict__ w2l,
    __nv_bfloat16* __restrict__ g2h, __nv_bfloat16* __restrict__ g2l)
{
    int i = blockIdx.x * blockDim.x + threadIdx.x;
    const float* src; __nv_bfloat16 *hi, *lo; int local, N;
    if (i < 65536)        { src = W1; hi = w1h; lo = w1l; local = i;          N = 256; }
    else if (i < 131072)  { src = G1; hi = g1h; lo = g1l; local = i - 65536;  N = 256; }
    else if (i < 163840)  { src = W2; hi = w2h; lo = w2l; local = i - 131072; N = 128; }
    else if (i < 196608)  { src = G2; hi = g2h; lo = g2l; local = i - 163840; N = 128; }
    else return;
    int n = local >> 8, k = local & 255;          // K = 256 contiguous in dst
    float w = src[(size_t)k * N + n];
    __nv_bfloat16 h = __float2bfloat16_rn(w);
    hi[local] = h;
    lo[local] = __float2bfloat16_rn(w - __bfloat162float(h));
}

// ---------------------------------------------------------------------------
// CSR build: histogram -> scan -> scatter
// ---------------------------------------------------------------------------
__global__ __launch_bounds__(256) void hist_kernel(
    const int* __restrict__ rows, int* __restrict__ cnt, int E)
{
    int e = blockIdx.x * blockDim.x + threadIdx.x;
    if (e < E) atomicAdd(&cnt[rows[e]], 1);
}

__global__ __launch_bounds__(1024) void scan_kernel(
    const int* __restrict__ cnt, int* __restrict__ rowptr, int n)
{
    __shared__ int warp_sums[32];
    __shared__ int s_carry;
    const int tid = threadIdx.x;
    const int lane = tid & 31, w = tid >> 5;
    if (tid == 0) { rowptr[0] = 0; s_carry = 0; }
    __syncthreads();

    for (int base = 0; base < n; base += 1024) {
        int i = base + tid;
        int v = (i < n) ? cnt[i] : 0;
        int s = v;
#pragma unroll
        for (int o = 1; o < 32; o <<= 1) {
            int t = __shfl_up_sync(0xffffffffu, s, o);
            if (lane >= o) s += t;
        }
        if (lane == 31) warp_sums[w] = s;
        __syncthreads();
        if (w == 0) {
            int ws = warp_sums[lane];
#pragma unroll
            for (int o = 1; o < 32; o <<= 1) {
                int t = __shfl_up_sync(0xffffffffu, ws, o);
                if (lane >= o) ws += t;
            }
            warp_sums[lane] = ws;
        }
        __syncthreads();
        int incl = s + (w > 0 ? warp_sums[w - 1] : 0) + s_carry;
        if (i < n) rowptr[i + 1] = incl;
        __syncthreads();
        if (tid == 1023) s_carry = incl;
        __syncthreads();
    }
}

__global__ __launch_bounds__(256) void scatter_kernel(
    const int* __restrict__ rows, const int* __restrict__ cols,
    const float* __restrict__ vals,
    const int* __restrict__ rowptr, int* __restrict__ cursor,
    int2* __restrict__ edges, int E)
{
    int e = blockIdx.x * blockDim.x + threadIdx.x;
    if (e >= E) return;
    int r = rows[e];
    int pos = rowptr[r] + atomicAdd(&cursor[r], 1);
    edges[pos] = make_int2(cols[e], __float_as_int(vals[e]));
}

// ---------------------------------------------------------------------------
// Single-matrix CSR pull-SpMM, epilogue splits fp32 accum -> bf16 hi/lo.
//   Z[r] = sum_e v_e * X[c_e]; D = 256 (64 float4 per row, 64 thr/row)
// Edge loop unrolled x4 for MLP.
// ---------------------------------------------------------------------------
__global__ __launch_bounds__(256) void spmm_split_kernel(
    const int*  __restrict__ rowptr, const int2* __restrict__ edges,
    const float4* __restrict__ X,
    __nv_bfloat16* __restrict__ Zh, __nv_bfloat16* __restrict__ Zl, int n)
{
    const int r = blockIdx.x * 4 + (threadIdx.x >> 6);
    const int j = threadIdx.x & 63;
    if (r >= n) return;

    const int beg = __ldg(&rowptr[r]);
    const int end = __ldg(&rowptr[r + 1]);

    float4 a = make_float4(0.f, 0.f, 0.f, 0.f);
    int i = beg;
    for (; i + 3 < end; i += 4) {
        int2 e0 = __ldg(&edges[i]);
        int2 e1 = __ldg(&edges[i + 1]);
        int2 e2 = __ldg(&edges[i + 2]);
        int2 e3 = __ldg(&edges[i + 3]);
        float4 s0 = __ldg(&X[(size_t)e0.x * 64 + j]);
        float4 s1 = __ldg(&X[(size_t)e1.x * 64 + j]);
        float4 s2 = __ldg(&X[(size_t)e2.x * 64 + j]);
        float4 s3 = __ldg(&X[(size_t)e3.x * 64 + j]);
        float v0 = __int_as_float(e0.y), v1 = __int_as_float(e1.y);
        float v2 = __int_as_float(e2.y), v3 = __int_as_float(e3.y);
        a.x = fmaf(v0, s0.x, a.x); a.y = fmaf(v0, s0.y, a.y);
        a.z = fmaf(v0, s0.z, a.z); a.w = fmaf(v0, s0.w, a.w);
        a.x = fmaf(v1, s1.x, a.x); a.y = fmaf(v1, s1.y, a.y);
        a.z = fmaf(v1, s1.z, a.z); a.w = fmaf(v1, s1.w, a.w);
        a.x = fmaf(v2, s2.x, a.x); a.y = fmaf(v2, s2.y, a.y);
        a.z = fmaf(v2, s2.z, a.z); a.w = fmaf(v2, s2.w, a.w);
        a.x = fmaf(v3, s3.x, a.x); a.y = fmaf(v3, s3.y, a.y);
        a.z = fmaf(v3, s3.z, a.z); a.w = fmaf(v3, s3.w, a.w);
    }
    for (; i < end; i++) {
        int2 e = __ldg(&edges[i]);
        const float v = __int_as_float(e.y);
        float4 s = __ldg(&X[(size_t)e.x * 64 + j]);
        a.x = fmaf(v, s.x, a.x); a.y = fmaf(v, s.y, a.y);
        a.z = fmaf(v, s.z, a.z); a.w = fmaf(v, s.w, a.w);
    }

    __nv_bfloat16 h0 = __float2bfloat16_rn(a.x);
    __nv_bfloat16 h1 = __float2bfloat16_rn(a.y);
    __nv_bfloat16 h2 = __float2bfloat16_rn(a.z);
    __nv_bfloat16 h3 = __float2bfloat16_rn(a.w);
    __nv_bfloat16 l0 = __float2bfloat16_rn(a.x - __bfloat162float(h0));
    __nv_bfloat16 l1 = __float2bfloat16_rn(a.y - __bfloat162float(h1));
    __nv_bfloat16 l2 = __float2bfloat16_rn(a.z - __bfloat162float(h2));
    __nv_bfloat16 l3 = __float2bfloat16_rn(a.w - __bfloat162float(h3));
    __nv_bfloat162 hh0 = __nv_bfloat162(h0, h1), hh1 = __nv_bfloat162(h2, h3);
    __nv_bfloat162 ll0 = __nv_bfloat162(l0, l1), ll1 = __nv_bfloat162(l2, l3);
    size_t o = (size_t)r * 256 + j * 4;
    *reinterpret_cast<uint2*>(&Zh[o]) = make_uint2(*(uint32_t*)&hh0, *(uint32_t*)&hh1);
    *reinterpret_cast<uint2*>(&Zl[o]) = make_uint2(*(uint32_t*)&ll0, *(uint32_t*)&ll1);
}

// ---------------------------------------------------------------------------
// Fused gated dual-GEMM:  O = act( sigmoid(Z@G) * (Z@W) )
//   Z: [M,256] bf16 hi/lo. W/G: [NOUT,256] bf16 hi/lo K-major.
//   CTA 128 rows x 64 cols. 8 warps: warp_m = wid&3 (32 rows),
//   warp_n = wid>>2 (32 cols); warp tile 32x32 per output = 2x4 m16n8.
//   KC=64, 2-stage cp.async pipeline, ldmatrix frags, PAD=72 halves (144B:
//   16B-aligned rows, 4-bank shift/row -> conflict-free ldmatrix).
// ---------------------------------------------------------------------------
template <int NOUT, bool RELU>
__global__ __launch_bounds__(256, 1) void gemm_gated_kernel(
    const __nv_bfloat16* __restrict__ Ah, const __nv_bfloat16* __restrict__ Al,
    const __nv_bfloat16* __restrict__ Wh, const __nv_bfloat16* __restrict__ Wl,
    const __nv_bfloat16* __restrict__ Gh, const __nv_bfloat16* __restrict__ Gl,
    float* __restrict__ O, int M)
{
    constexpr int K = 256, KC = 64, NCH = K / KC;   // 4 chunks
    constexpr int ROW  = 72;                        // padded row (halves)
    constexpr int A_LO = 128 * ROW;                 // 9216 halves
    constexpr int B0   = 2 * A_LO;                  // 18432
    constexpr int BM   = 64 * ROW;                  // 4608 per B matrix
    constexpr int STG  = B0 + 4 * BM;               // 36864 halves per stage

    extern __shared__ __align__(16) __nv_bfloat16 dsm[];
    const uint32_t sb =
        (uint32_t)__cvta_generic_to_shared(dsm);

    const int tid  = threadIdx.x;
    const int wid  = tid >> 5;
    const int lane = tid & 31;
    const int warp_m = wid & 3;
    const int warp_n = wid >> 2;
    const int row0 = blockIdx.y * 128;
    const int col0 = blockIdx.x * 64;

    const __nv_bfloat16* bsrc[4] = {Wh, Wl, Gh, Gl};

    // ---- stage loader: chunk c into stage s ----
    auto load_stage = [&](int s, int c) {
        const int k0 = c * KC;
        const uint32_t base = sb + (uint32_t)(s * STG) * 2;
#pragma unroll
        for (int it = 0; it < 4; it++) {            // A hi+lo: 1024 vec16 each
            int i = tid + it * 256;
            int r = i >> 3, v = i & 7;
            int grow = row0 + r;
            uint32_t sz = (grow < M) ? 16u : 0u;
            int gclamp = (grow < M) ? grow : (M - 1);
            size_t go = (size_t)gclamp * K + k0 + v * 8;
            uint32_t so = (uint32_t)(r * ROW + v * 8) * 2;
            cpasync16(base + so, &Ah[go], sz);
            cpasync16(base + (uint32_t)A_LO * 2 + so, &Al[go], sz);
        }
#pragma unroll
        for (int m = 0; m < 4; m++) {               // B: 4 x 512 vec16
#pragma unroll
            for (int it = 0; it < 2; it++) {
                int i = tid + it * 256;
                int r = i >> 3, v = i & 7;
                size_t go = (size_t)(col0 + r) * K + k0 + v * 8;
                uint32_t so = (uint32_t)(B0 + m * BM + r * ROW + v * 8) * 2;
                cpasync16(base + so, &bsrc[m][go], 16u);
            }
        }
        cpcommit();
    };

    float accS[2][4][4], accT[2][4][4];
#pragma unroll
    for (int i = 0; i < 2; i++)
#pragma unroll
        for (int j = 0; j < 4; j++)
#pragma unroll
            for (int q = 0; q < 4; q++) { accS[i][j][q] = 0.f; accT[i][j][q] = 0.f; }

    load_stage(0, 0);

    for (int c = 0; c < NCH; c++) {
        if (c + 1 < NCH) {
            load_stage((c + 1) & 1, c + 1);
            cpwait<1>();
        } else {
            cpwait<0>();
        }
        __syncthreads();

        const uint32_t base = sb + (uint32_t)((c & 1) * STG) * 2;
#pragma unroll
        for (int ks = 0; ks < KC / 16; ks++) {
            // A fragments (hi/lo) via ldmatrix.x4
            uint32_t ah[2][4], al[2][4];
#pragma unroll
            for (int mt = 0; mt < 2; mt++) {
                uint32_t ra = base + (uint32_t)(
                    (warp_m * 32 + mt * 16 + (lane & 15)) * ROW +
                    ks * 16 + (lane >> 4) * 8) * 2;
                ldmx4(ah[mt], ra);
                ldmx4(al[mt], ra + (uint32_t)A_LO * 2);
            }
            // B fragments via ldmatrix.x2
            uint32_t wh[4][2], wl[4][2], gh[4][2], gl[4][2];
#pragma unroll
            for (int nt = 0; nt < 4; nt++) {
                uint32_t rb = base + (uint32_t)(B0 +
                    (warp_n * 32 + nt * 8 + (lane & 7)) * ROW +
                    ks * 16 + ((lane >> 3) & 1) * 8) * 2;
                ldmx2(wh[nt], rb);
                ldmx2(wl[nt], rb + (uint32_t)BM * 2);
                ldmx2(gh[nt], rb + (uint32_t)(2 * BM) * 2);
                ldmx2(gl[nt], rb + (uint32_t)(3 * BM) * 2);
            }
#pragma unroll
            for (int mt = 0; mt < 2; mt++)
#pragma unroll
                for (int nt = 0; nt < 4; nt++) {
                    mma16816(accS[mt][nt], ah[mt], wh[nt]);
                    mma16816(accS[mt][nt], ah[mt], wl[nt]);
                    mma16816(accS[mt][nt], al[mt], wh[nt]);
                    mma16816(accT[mt][nt], ah[mt], gh[nt]);
                    mma16816(accT[mt][nt], ah[mt], gl[nt]);
                    mma16816(accT[mt][nt], al[mt], gh[nt]);
                }
        }
        __syncthreads();
    }

    // ---- gated epilogue ----
#pragma unroll
    for (int mt = 0; mt < 2; mt++) {
        int r_lo = row0 + warp_m * 32 + mt * 16 + (lane >> 2);
#pragma unroll
        for (int nt = 0; nt < 4; nt++) {
            int n = col0 + warp_n * 32 + nt * 8 + (lane & 3) * 2;
            float o0 = sigmoidf_(accT[mt][nt][0]) * accS[mt][nt][0];
            float o1 = sigmoidf_(accT[mt][nt][1]) * accS[mt][nt][1];
            float o2 = sigmoidf_(accT[mt][nt][2]) * accS[mt][nt][2];
            float o3 = sigmoidf_(accT[mt][nt][3]) * accS[mt][nt][3];
            if (RELU) {
                o0 = fmaxf(o0, 0.f); o1 = fmaxf(o1, 0.f);
                o2 = fmaxf(o2, 0.f); o3 = fmaxf(o3, 0.f);
            }
            if (r_lo < M)
                *reinterpret_cast<float2*>(&O[(size_t)r_lo * NOUT + n]) =
                    make_float2(o0, o1);
            if (r_lo + 8 < M)
                *reinterpret_cast<float2*>(&O[(size_t)(r_lo + 8) * NOUT + n]) =
                    make_float2(o2, o3);
        }
    }
}

// ---------------------------------------------------------------------------
// Launcher (graph-capturable)
// ---------------------------------------------------------------------------
extern "C" void kernel_launch(void* const* d_in, const int* in_sizes, int n_in,
                              void* d_out, int out_size)
{
    const float* x    = (const float*)d_in[0];
    const int*   rows = (const int*)  d_in[1];
    const int*   cols = (const int*)  d_in[2];
    const float* vals = (const float*)d_in[3];
    const float* W1   = (const float*)d_in[4];
    const float* G1   = (const float*)d_in[5];
    const float* W2   = (const float*)d_in[6];
    const float* G2   = (const float*)d_in[7];
    float* out = (float*)d_out;

    __nv_bfloat16 *Zh, *Zl, *w1h, *w1l, *g1h, *g1l, *w2h, *w2l, *g2h, *g2l;
    float* h;
    int *rowptr, *cnt;
    int2 *edges;
    cudaGetSymbolAddress((void**)&Zh,     g_Zh);
    cudaGetSymbolAddress((void**)&Zl,     g_Zl);
    cudaGetSymbolAddress((void**)&h,      g_h);
    cudaGetSymbolAddress((void**)&w1h,    g_w1h);
    cudaGetSymbolAddress((void**)&w1l,    g_w1l);
    cudaGetSymbolAddress((void**)&g1h,    g_g1h);
    cudaGetSymbolAddress((void**)&g1l,    g_g1l);
    cudaGetSymbolAddress((void**)&w2h,    g_w2h);
    cudaGetSymbolAddress((void**)&w2l,    g_w2l);
    cudaGetSymbolAddress((void**)&g2h,    g_g2h);
    cudaGetSymbolAddress((void**)&g2l,    g_g2l);
    cudaGetSymbolAddress((void**)&rowptr, g_rowptr);
    cudaGetSymbolAddress((void**)&cnt,    g_cnt);
    cudaGetSymbolAddress((void**)&edges,  g_edges);

    const int M  = N_NODES;
    const int EB = (E_EDGES + 255) / 256;
    const int MT = (M + 127) / 128;                 // 391 M-tiles

    constexpr int GSMEM = 2 * 36864 * 2;            // 147456 B
    cudaFuncSetAttribute(gemm_gated_kernel<D_HID, true>,
                         cudaFuncAttributeMaxDynamicSharedMemorySize, GSMEM);
    cudaFuncSetAttribute(gemm_gated_kernel<D_OUT, false>,
                         cudaFuncAttributeMaxDynamicSharedMemorySize, GSMEM);

    // -------- CSR build --------
    cudaMemsetAsync(cnt, 0, N_NODES * sizeof(int));
    hist_kernel<<<EB, 256>>>(rows, cnt, E_EDGES);
    scan_kernel<<<1, 1024>>>(cnt, rowptr, N_NODES);
    cudaMemsetAsync(cnt, 0, N_NODES * sizeof(int));
    scatter_kernel<<<EB, 256>>>(rows, cols, vals, rowptr, cnt, edges, E_EDGES);

    // -------- weight prep (one launch) --------
    wsplit_all_kernel<<<768, 256>>>(W1, G1, W2, G2,
                                    w1h, w1l, g1h, g1l, w2h, w2l, g2h, g2l);

    // -------- Layer 1: Z = spmm(adj, x); h = relu(sig(Z@G1)*(Z@W1)) --------
    spmm_split_kernel<<<(M + 3) / 4, 256>>>(rowptr, edges, (const float4*)x,
                                            Zh, Zl, M);
    gemm_gated_kernel<D_HID, true><<<dim3(D_HID / 64, MT), 256, GSMEM>>>(
        Zh, Zl, w1h, w1l, g1h, g1l, h, M);

    // -------- Layer 2: Z = spmm(adj, h); out = sig(Z@G2)*(Z@W2) --------
    spmm_split_kernel<<<(M + 3) / 4, 256>>>(rowptr, edges, (const float4*)h,
                                            Zh, Zl, M);
    gemm_gated_kernel<D_OUT, false><<<dim3(D_OUT / 64, MT), 256, GSMEM>>>(
        Zh, Zl, w2h, w2l, g2h, g2l, out, M);
}

// round 9
// speedup vs baseline: 3.3755x; 1.1389x over previous
#include <cuda_runtime.h>
#include <cuda_bf16.h>
#include <cstdint>

// ============================================================================
// GatedGCN on GB300 (compute_103 PTX -> mma.sync HMMA + cp.async + ldmatrix).
// Identity: spmm(adj, x@W) = spmm(adj, x)@W
//   per layer: Z = spmm(adj, X); out = act(sigmoid(Z@G) * (Z@W))
//   - single-matrix CSR pull-SpMM (epilogue emits bf16 hi/lo)
//   - fused gated dual-GEMM: 128x128 CTA tile, 512 thr, bf16 3-term comp,
//     cp.async double-buffer, ldmatrix, gating epilogue in-register.
//   - CSR build with parallel 3-phase scan.
// ============================================================================

#define N_NODES 50000
#define E_EDGES 800000
#define D_IN    256
#define D_HID   256
#define D_OUT   128

// ---------------------------------------------------------------------------
// Scratch (device globals: allocation-free rule)
// ---------------------------------------------------------------------------
__device__ __nv_bfloat16 g_Zh [(size_t)N_NODES * 256];   // spmm out hi
__device__ __nv_bfloat16 g_Zl [(size_t)N_NODES * 256];   // spmm out lo
__device__ float         g_h  [(size_t)N_NODES * D_HID]; // hidden activation
__device__ __nv_bfloat16 g_w1h[D_HID * D_IN], g_w1l[D_HID * D_IN];   // Wt [N,K]
__device__ __nv_bfloat16 g_g1h[D_HID * D_IN], g_g1l[D_HID * D_IN];
__device__ __nv_bfloat16 g_w2h[D_OUT * D_HID], g_w2l[D_OUT * D_HID];
__device__ __nv_bfloat16 g_g2h[D_OUT * D_HID], g_g2l[D_OUT * D_HID];
__device__ int   g_rowptr[N_NODES + 1];
__device__ int   g_cnt   [N_NODES];
__device__ int   g_blk   [64];
__device__ int2  g_edges [E_EDGES];

// ---------------------------------------------------------------------------
// PTX helpers
// ---------------------------------------------------------------------------
__device__ __forceinline__ void mma16816(float* c, const uint32_t* a,
                                         const uint32_t* b) {
    asm volatile(
        "mma.sync.aligned.m16n8k16.row.col.f32.bf16.bf16.f32 "
        "{%0,%1,%2,%3}, {%4,%5,%6,%7}, {%8,%9}, {%0,%1,%2,%3};"
        : "+f"(c[0]), "+f"(c[1]), "+f"(c[2]), "+f"(c[3])
        : "r"(a[0]), "r"(a[1]), "r"(a[2]), "r"(a[3]), "r"(b[0]), "r"(b[1]));
}
__device__ __forceinline__ void ldmx4(uint32_t* r, uint32_t addr) {
    asm volatile("ldmatrix.sync.aligned.m8n8.x4.shared.b16 {%0,%1,%2,%3}, [%4];"
                 : "=r"(r[0]), "=r"(r[1]), "=r"(r[2]), "=r"(r[3]) : "r"(addr));
}
__device__ __forceinline__ void ldmx2(uint32_t* r, uint32_t addr) {
    asm volatile("ldmatrix.sync.aligned.m8n8.x2.shared.b16 {%0,%1}, [%2];"
                 : "=r"(r[0]), "=r"(r[1]) : "r"(addr));
}
__device__ __forceinline__ void cpasync16(uint32_t sdst, const void* gsrc,
                                          uint32_t sz) {
    asm volatile("cp.async.cg.shared.global [%0], [%1], 16, %2;"
                 :: "r"(sdst), "l"(gsrc), "r"(sz));
}
__device__ __forceinline__ void cpcommit() {
    asm volatile("cp.async.commit_group;");
}
template <int N>
__device__ __forceinline__ void cpwait() {
    asm volatile("cp.async.wait_group %0;" :: "n"(N));
}
__device__ __forceinline__ float sigmoidf_(float x) {
    return 1.f / (1.f + expf(-x));
}

// ---------------------------------------------------------------------------
// All-weights transpose+split in ONE launch
// ---------------------------------------------------------------------------
__global__ __launch_bounds__(256) void wsplit_all_kernel(
    const float* __restrict__ W1, const float* __restrict__ G1,
    const float* __restrict__ W2, const float* __restrict__ G2,
    __nv_bfloat16* __restrict__ w1h, __nv_bfloat16* __restrict__ w1l,
    __nv_bfloat16* __restrict__ g1h, __nv_bfloat16* __restrict__ g1l,
    __nv_bfloat16* __restrict__ w2h, __nv_bfloat16* __restrict__ w2l,
    __nv_bfloat16* __restrict__ g2h, __nv_bfloat16* __restrict__ g2l)
{
    int i = blockIdx.x * blockDim.x + threadIdx.x;
    const float* src; __nv_bfloat16 *hi, *lo; int local, N;
    if (i < 65536)        { src = W1; hi = w1h; lo = w1l; local = i;          N = 256; }
    else if (i < 131072)  { src = G1; hi = g1h; lo = g1l; local = i - 65536;  N = 256; }
    else if (i < 163840)  { src = W2; hi = w2h; lo = w2l; local = i - 131072; N = 128; }
    else if (i < 196608)  { src = G2; hi = g2h; lo = g2l; local = i - 163840; N = 128; }
    else return;
    int n = local >> 8, k = local & 255;
    float w = src[(size_t)k * N + n];
    __nv_bfloat16 h = __float2bfloat16_rn(w);
    hi[local] = h;
    lo[local] = __float2bfloat16_rn(w - __bfloat162float(h));
}

// ---------------------------------------------------------------------------
// CSR build: histogram -> 3-phase parallel scan -> scatter
// ---------------------------------------------------------------------------
__global__ __launch_bounds__(256) void hist_kernel(
    const int* __restrict__ rows, int* __restrict__ cnt, int E)
{
    int e = blockIdx.x * blockDim.x + threadIdx.x;
    if (e < E) atomicAdd(&cnt[rows[e]], 1);
}

// Phase A: per-block inclusive scan of 1024 counters; block total -> blk[b]
__global__ __launch_bounds__(1024) void scanA_kernel(
    const int* __restrict__ cnt, int* __restrict__ rowptr,
    int* __restrict__ blk, int n)
{
    __shared__ int warp_sums[32];
    const int tid = threadIdx.x, lane = tid & 31, w = tid >> 5;
    int i = blockIdx.x * 1024 + tid;
    int v = (i < n) ? cnt[i] : 0;
    int s = v;
#pragma unroll
    for (int o = 1; o < 32; o <<= 1) {
        int t = __shfl_up_sync(0xffffffffu, s, o);
        if (lane >= o) s += t;
    }
    if (lane == 31) warp_sums[w] = s;
    __syncthreads();
    if (w == 0) {
        int ws = warp_sums[lane];
#pragma unroll
        for (int o = 1; o < 32; o <<= 1) {
            int t = __shfl_up_sync(0xffffffffu, ws, o);
            if (lane >= o) ws += t;
        }
        warp_sums[lane] = ws;
    }
    __syncthreads();
    int incl = s + (w > 0 ? warp_sums[w - 1] : 0);
    if (i < n) rowptr[i + 1] = incl;
    if (tid == 1023) blk[blockIdx.x] = incl;
}

// Phase B: exclusive scan of block sums (small, single thread)
__global__ void scanB_kernel(int* __restrict__ blk, int nb)
{
    if (threadIdx.x == 0 && blockIdx.x == 0) {
        int acc = 0;
        for (int b = 0; b < nb; b++) { int t = blk[b]; blk[b] = acc; acc += t; }
    }
}

// Phase C: add block offsets; set rowptr[0]
__global__ __launch_bounds__(1024) void scanC_kernel(
    int* __restrict__ rowptr, const int* __restrict__ blk, int n)
{
    int i = blockIdx.x * 1024 + threadIdx.x;
    if (i < n) rowptr[i + 1] += blk[blockIdx.x];
    if (i == 0) rowptr[0] = 0;
}

__global__ __launch_bounds__(256) void scatter_kernel(
    const int* __restrict__ rows, const int* __restrict__ cols,
    const float* __restrict__ vals,
    const int* __restrict__ rowptr, int* __restrict__ cursor,
    int2* __restrict__ edges, int E)
{
    int e = blockIdx.x * blockDim.x + threadIdx.x;
    if (e >= E) return;
    int r = rows[e];
    int pos = rowptr[r] + atomicAdd(&cursor[r], 1);
    edges[pos] = make_int2(cols[e], __float_as_int(vals[e]));
}

// ---------------------------------------------------------------------------
// Single-matrix CSR pull-SpMM, epilogue splits fp32 accum -> bf16 hi/lo.
// ---------------------------------------------------------------------------
__global__ __launch_bounds__(256) void spmm_split_kernel(
    const int*  __restrict__ rowptr, const int2* __restrict__ edges,
    const float4* __restrict__ X,
    __nv_bfloat16* __restrict__ Zh, __nv_bfloat16* __restrict__ Zl, int n)
{
    const int r = blockIdx.x * 4 + (threadIdx.x >> 6);
    const int j = threadIdx.x & 63;
    if (r >= n) return;

    const int beg = __ldg(&rowptr[r]);
    const int end = __ldg(&rowptr[r + 1]);

    float4 a = make_float4(0.f, 0.f, 0.f, 0.f);
    int i = beg;
    for (; i + 3 < end; i += 4) {
        int2 e0 = __ldg(&edges[i]);
        int2 e1 = __ldg(&edges[i + 1]);
        int2 e2 = __ldg(&edges[i + 2]);
        int2 e3 = __ldg(&edges[i + 3]);
        float4 s0 = __ldg(&X[(size_t)e0.x * 64 + j]);
        float4 s1 = __ldg(&X[(size_t)e1.x * 64 + j]);
        float4 s2 = __ldg(&X[(size_t)e2.x * 64 + j]);
        float4 s3 = __ldg(&X[(size_t)e3.x * 64 + j]);
        float v0 = __int_as_float(e0.y), v1 = __int_as_float(e1.y);
        float v2 = __int_as_float(e2.y), v3 = __int_as_float(e3.y);
        a.x = fmaf(v0, s0.x, a.x); a.y = fmaf(v0, s0.y, a.y);
        a.z = fmaf(v0, s0.z, a.z); a.w = fmaf(v0, s0.w, a.w);
        a.x = fmaf(v1, s1.x, a.x); a.y = fmaf(v1, s1.y, a.y);
        a.z = fmaf(v1, s1.z, a.z); a.w = fmaf(v1, s1.w, a.w);
        a.x = fmaf(v2, s2.x, a.x); a.y = fmaf(v2, s2.y, a.y);
        a.z = fmaf(v2, s2.z, a.z); a.w = fmaf(v2, s2.w, a.w);
        a.x = fmaf(v3, s3.x, a.x); a.y = fmaf(v3, s3.y, a.y);
        a.z = fmaf(v3, s3.z, a.z); a.w = fmaf(v3, s3.w, a.w);
    }
    for (; i < end; i++) {
        int2 e = __ldg(&edges[i]);
        const float v = __int_as_float(e.y);
        float4 s = __ldg(&X[(size_t)e.x * 64 + j]);
        a.x = fmaf(v, s.x, a.x); a.y = fmaf(v, s.y, a.y);
        a.z = fmaf(v, s.z, a.z); a.w = fmaf(v, s.w, a.w);
    }

    __nv_bfloat16 h0 = __float2bfloat16_rn(a.x);
    __nv_bfloat16 h1 = __float2bfloat16_rn(a.y);
    __nv_bfloat16 h2 = __float2bfloat16_rn(a.z);
    __nv_bfloat16 h3 = __float2bfloat16_rn(a.w);
    __nv_bfloat16 l0 = __float2bfloat16_rn(a.x - __bfloat162float(h0));
    __nv_bfloat16 l1 = __float2bfloat16_rn(a.y - __bfloat162float(h1));
    __nv_bfloat16 l2 = __float2bfloat16_rn(a.z - __bfloat162float(h2));
    __nv_bfloat16 l3 = __float2bfloat16_rn(a.w - __bfloat162float(h3));
    __nv_bfloat162 hh0 = __nv_bfloat162(h0, h1), hh1 = __nv_bfloat162(h2, h3);
    __nv_bfloat162 ll0 = __nv_bfloat162(l0, l1), ll1 = __nv_bfloat162(l2, l3);
    size_t o = (size_t)r * 256 + j * 4;
    *reinterpret_cast<uint2*>(&Zh[o]) = make_uint2(*(uint32_t*)&hh0, *(uint32_t*)&hh1);
    *reinterpret_cast<uint2*>(&Zl[o]) = make_uint2(*(uint32_t*)&ll0, *(uint32_t*)&ll1);
}

// ---------------------------------------------------------------------------
// Fused gated dual-GEMM:  O = act( sigmoid(Z@G) * (Z@W) )
//   Z: [M,256] bf16 hi/lo. W/G: [NOUT,256] bf16 hi/lo K-major.
//   CTA 128 rows x 128 cols (of both W and G), 512 threads / 16 warps:
//   warp_m = wid&3 (32 rows), warp_n = wid>>2 (32 cols); warp tile 32x32
//   per output = 2x4 m16n8 tiles; 3-term compensation.
//   KC=64, 2-stage cp.async pipeline, ldmatrix frags, ROW=72-half padding.
// ---------------------------------------------------------------------------
template <int NOUT, bool RELU>
__global__ __launch_bounds__(512, 1) void gemm_gated_kernel(
    const __nv_bfloat16* __restrict__ Ah, const __nv_bfloat16* __restrict__ Al,
    const __nv_bfloat16* __restrict__ Wh, const __nv_bfloat16* __restrict__ Wl,
    const __nv_bfloat16* __restrict__ Gh, const __nv_bfloat16* __restrict__ Gl,
    float* __restrict__ O, int M)
{
    constexpr int K = 256, KC = 64, NCH = K / KC;   // 4 chunks
    constexpr int ROW  = 72;                        // padded row (halves)
    constexpr int TMAT = 128 * ROW;                 // 9216 halves per matrix
    constexpr int B0   = 2 * TMAT;                  // after Ah, Al
    constexpr int STG  = B0 + 4 * TMAT;             // 55296 halves per stage

    extern __shared__ __align__(16) __nv_bfloat16 dsm[];
    const uint32_t sb = (uint32_t)__cvta_generic_to_shared(dsm);

    const int tid  = threadIdx.x;
    const int wid  = tid >> 5;
    const int lane = tid & 31;
    const int warp_m = wid & 3;
    const int warp_n = wid >> 2;
    const int row0 = blockIdx.y * 128;
    const int col0 = blockIdx.x * 128;

    const __nv_bfloat16* bsrc[4] = {Wh, Wl, Gh, Gl};

    auto load_stage = [&](int s, int c) {
        const int k0 = c * KC;
        const uint32_t base = sb + (uint32_t)(s * STG) * 2;
#pragma unroll
        for (int it = 0; it < 2; it++) {            // A hi+lo: 1024 vec16 each
            int i = tid + it * 512;
            int r = i >> 3, v = i & 7;
            int grow = row0 + r;
            uint32_t sz = (grow < M) ? 16u : 0u;
            int gclamp = (grow < M) ? grow : (M - 1);
            size_t go = (size_t)gclamp * K + k0 + v * 8;
            uint32_t so = (uint32_t)(r * ROW + v * 8) * 2;
            cpasync16(base + so, &Ah[go], sz);
            cpasync16(base + (uint32_t)TMAT * 2 + so, &Al[go], sz);
        }
#pragma unroll
        for (int m = 0; m < 4; m++) {               // B: 4 x 1024 vec16
#pragma unroll
            for (int it = 0; it < 2; it++) {
                int i = tid + it * 512;
                int r = i >> 3, v = i & 7;
                size_t go = (size_t)(col0 + r) * K + k0 + v * 8;
                uint32_t so = (uint32_t)(B0 + m * TMAT + r * ROW + v * 8) * 2;
                cpasync16(base + so, &bsrc[m][go], 16u);
            }
        }
        cpcommit();
    };

    float accS[2][4][4], accT[2][4][4];
#pragma unroll
    for (int i = 0; i < 2; i++)
#pragma unroll
        for (int j = 0; j < 4; j++)
#pragma unroll
            for (int q = 0; q < 4; q++) { accS[i][j][q] = 0.f; accT[i][j][q] = 0.f; }

    load_stage(0, 0);

    for (int c = 0; c < NCH; c++) {
        if (c + 1 < NCH) {
            load_stage((c + 1) & 1, c + 1);
            cpwait<1>();
        } else {
            cpwait<0>();
        }
        __syncthreads();

        const uint32_t base = sb + (uint32_t)((c & 1) * STG) * 2;
#pragma unroll
        for (int ks = 0; ks < KC / 16; ks++) {
            uint32_t ah[2][4], al[2][4];
#pragma unroll
            for (int mt = 0; mt < 2; mt++) {
                uint32_t ra = base + (uint32_t)(
                    (warp_m * 32 + mt * 16 + (lane & 15)) * ROW +
                    ks * 16 + (lane >> 4) * 8) * 2;
                ldmx4(ah[mt], ra);
                ldmx4(al[mt], ra + (uint32_t)TMAT * 2);
            }
            uint32_t wh[4][2], wl[4][2], gh[4][2], gl[4][2];
#pragma unroll
            for (int nt = 0; nt < 4; nt++) {
                uint32_t rb = base + (uint32_t)(B0 +
                    (warp_n * 32 + nt * 8 + (lane & 7)) * ROW +
                    ks * 16 + ((lane >> 3) & 1) * 8) * 2;
                ldmx2(wh[nt], rb);
                ldmx2(wl[nt], rb + (uint32_t)TMAT * 2);
                ldmx2(gh[nt], rb + (uint32_t)(2 * TMAT) * 2);
                ldmx2(gl[nt], rb + (uint32_t)(3 * TMAT) * 2);
            }
#pragma unroll
            for (int mt = 0; mt < 2; mt++)
#pragma unroll
                for (int nt = 0; nt < 4; nt++) {
                    mma16816(accS[mt][nt], ah[mt], wh[nt]);
                    mma16816(accS[mt][nt], ah[mt], wl[nt]);
                    mma16816(accS[mt][nt], al[mt], wh[nt]);
                    mma16816(accT[mt][nt], ah[mt], gh[nt]);
                    mma16816(accT[mt][nt], ah[mt], gl[nt]);
                    mma16816(accT[mt][nt], al[mt], gh[nt]);
                }
        }
        __syncthreads();
    }

    // ---- gated epilogue ----
#pragma unroll
    for (int mt = 0; mt < 2; mt++) {
        int r_lo = row0 + warp_m * 32 + mt * 16 + (lane >> 2);
#pragma unroll
        for (int nt = 0; nt < 4; nt++) {
            int n = col0 + warp_n * 32 + nt * 8 + (lane & 3) * 2;
            float o0 = sigmoidf_(accT[mt][nt][0]) * accS[mt][nt][0];
            float o1 = sigmoidf_(accT[mt][nt][1]) * accS[mt][nt][1];
            float o2 = sigmoidf_(accT[mt][nt][2]) * accS[mt][nt][2];
            float o3 = sigmoidf_(accT[mt][nt][3]) * accS[mt][nt][3];
            if (RELU) {
                o0 = fmaxf(o0, 0.f); o1 = fmaxf(o1, 0.f);
                o2 = fmaxf(o2, 0.f); o3 = fmaxf(o3, 0.f);
            }
            if (r_lo < M)
                *reinterpret_cast<float2*>(&O[(size_t)r_lo * NOUT + n]) =
                    make_float2(o0, o1);
            if (r_lo + 8 < M)
                *reinterpret_cast<float2*>(&O[(size_t)(r_lo + 8) * NOUT + n]) =
                    make_float2(o2, o3);
        }
    }
}

// ---------------------------------------------------------------------------
// Launcher (graph-capturable)
// ---------------------------------------------------------------------------
extern "C" void kernel_launch(void* const* d_in, const int* in_sizes, int n_in,
                              void* d_out, int out_size)
{
    const float* x    = (const float*)d_in[0];
    const int*   rows = (const int*)  d_in[1];
    const int*   cols = (const int*)  d_in[2];
    const float* vals = (const float*)d_in[3];
    const float* W1   = (const float*)d_in[4];
    const float* G1   = (const float*)d_in[5];
    const float* W2   = (const float*)d_in[6];
    const float* G2   = (const float*)d_in[7];
    float* out = (float*)d_out;

    __nv_bfloat16 *Zh, *Zl, *w1h, *w1l, *g1h, *g1l, *w2h, *w2l, *g2h, *g2l;
    float* h;
    int *rowptr, *cnt, *blk;
    int2 *edges;
    cudaGetSymbolAddress((void**)&Zh,     g_Zh);
    cudaGetSymbolAddress((void**)&Zl,     g_Zl);
    cudaGetSymbolAddress((void**)&h,      g_h);
    cudaGetSymbolAddress((void**)&w1h,    g_w1h);
    cudaGetSymbolAddress((void**)&w1l,    g_w1l);
    cudaGetSymbolAddress((void**)&g1h,    g_g1h);
    cudaGetSymbolAddress((void**)&g1l,    g_g1l);
    cudaGetSymbolAddress((void**)&w2h,    g_w2h);
    cudaGetSymbolAddress((void**)&w2l,    g_w2l);
    cudaGetSymbolAddress((void**)&g2h,    g_g2h);
    cudaGetSymbolAddress((void**)&g2l,    g_g2l);
    cudaGetSymbolAddress((void**)&rowptr, g_rowptr);
    cudaGetSymbolAddress((void**)&cnt,    g_cnt);
    cudaGetSymbolAddress((void**)&blk,    g_blk);
    cudaGetSymbolAddress((void**)&edges,  g_edges);

    const int M  = N_NODES;
    const int EB = (E_EDGES + 255) / 256;
    const int MT = (M + 127) / 128;                 // 391 M-tiles
    const int NB = (M + 1023) / 1024;               // 49 scan blocks

    constexpr int GSMEM = 2 * 55296 * 2;            // 221184 B
    cudaFuncSetAttribute(gemm_gated_kernel<D_HID, true>,
                         cudaFuncAttributeMaxDynamicSharedMemorySize, GSMEM);
    cudaFuncSetAttribute(gemm_gated_kernel<D_OUT, false>,
                         cudaFuncAttributeMaxDynamicSharedMemorySize, GSMEM);

    // -------- CSR build --------
    cudaMemsetAsync(cnt, 0, N_NODES * sizeof(int));
    hist_kernel<<<EB, 256>>>(rows, cnt, E_EDGES);
    scanA_kernel<<<NB, 1024>>>(cnt, rowptr, blk, N_NODES);
    scanB_kernel<<<1, 32>>>(blk, NB);
    scanC_kernel<<<NB, 1024>>>(rowptr, blk, N_NODES);
    cudaMemsetAsync(cnt, 0, N_NODES * sizeof(int));
    scatter_kernel<<<EB, 256>>>(rows, cols, vals, rowptr, cnt, edges, E_EDGES);

    // -------- weight prep (one launch) --------
    wsplit_all_kernel<<<768, 256>>>(W1, G1, W2, G2,
                                    w1h, w1l, g1h, g1l, w2h, w2l, g2h, g2l);

    // -------- Layer 1: Z = spmm(adj, x); h = relu(sig(Z@G1)*(Z@W1)) --------
    spmm_split_kernel<<<(M + 3) / 4, 256>>>(rowptr, edges, (const float4*)x,
                                            Zh, Zl, M);
    gemm_gated_kernel<D_HID, true><<<dim3(D_HID / 128, MT), 512, GSMEM>>>(
        Zh, Zl, w1h, w1l, g1h, g1l, h, M);

    // -------- Layer 2: Z = spmm(adj, h); out = sig(Z@G2)*(Z@W2) --------
    spmm_split_kernel<<<(M + 3) / 4, 256>>>(rowptr, edges, (const float4*)h,
                                            Zh, Zl, M);
    gemm_gated_kernel<D_OUT, false><<<dim3(D_OUT / 128, MT), 512, GSMEM>>>(
        Zh, Zl, w2h, w2l, g2h, g2l, out, M);
}

// round 10
// speedup vs baseline: 4.2891x; 1.2706x over previous
#include <cuda_runtime.h>
#include <cuda_fp16.h>
#include <cstdint>

// ============================================================================
// GatedGCN on GB300 (compute_103 PTX -> mma.sync HMMA + cp.async + ldmatrix).
// Identity: spmm(adj, x@W) = spmm(adj, x)@W
//   per layer: Z = spmm(adj, X); out = act(sigmoid(Z@G) * (Z@W))
// Precision scheme (fp16): Z quantized to single fp16 (~2^-12), weights split
// into fp16 hi+lo (exact to 2^-24) -> 2 MMA terms per output (was 3).
// Hidden activation h stored fp16 -> layer-2 gather traffic halved.
// ============================================================================

#define N_NODES 50000
#define E_EDGES 800000
#define D_IN    256
#define D_HID   256
#define D_OUT   128

// ---------------------------------------------------------------------------
// Scratch (device globals: allocation-free rule)
// ---------------------------------------------------------------------------
__device__ __half g_Z  [(size_t)N_NODES * 256];   // spmm out (fp16), reused
__device__ __half g_h  [(size_t)N_NODES * D_HID]; // hidden activation (fp16)
__device__ __half g_w1h[D_HID * D_IN], g_w1l[D_HID * D_IN];   // Wt [N,K] fp16
__device__ __half g_g1h[D_HID * D_IN], g_g1l[D_HID * D_IN];
__device__ __half g_w2h[D_OUT * D_HID], g_w2l[D_OUT * D_HID];
__device__ __half g_g2h[D_OUT * D_HID], g_g2l[D_OUT * D_HID];
__device__ int   g_rowptr[N_NODES + 1];
__device__ int   g_cnt   [N_NODES];
__device__ int   g_blk   [64];
__device__ int2  g_edges [E_EDGES];

// ---------------------------------------------------------------------------
// PTX helpers
// ---------------------------------------------------------------------------
__device__ __forceinline__ void mma16816(float* c, const uint32_t* a,
                                         const uint32_t* b) {
    asm volatile(
        "mma.sync.aligned.m16n8k16.row.col.f32.f16.f16.f32 "
        "{%0,%1,%2,%3}, {%4,%5,%6,%7}, {%8,%9}, {%0,%1,%2,%3};"
        : "+f"(c[0]), "+f"(c[1]), "+f"(c[2]), "+f"(c[3])
        : "r"(a[0]), "r"(a[1]), "r"(a[2]), "r"(a[3]), "r"(b[0]), "r"(b[1]));
}
__device__ __forceinline__ void ldmx4(uint32_t* r, uint32_t addr) {
    asm volatile("ldmatrix.sync.aligned.m8n8.x4.shared.b16 {%0,%1,%2,%3}, [%4];"
                 : "=r"(r[0]), "=r"(r[1]), "=r"(r[2]), "=r"(r[3]) : "r"(addr));
}
__device__ __forceinline__ void ldmx2(uint32_t* r, uint32_t addr) {
    asm volatile("ldmatrix.sync.aligned.m8n8.x2.shared.b16 {%0,%1}, [%2];"
                 : "=r"(r[0]), "=r"(r[1]) : "r"(addr));
}
__device__ __forceinline__ void cpasync16(uint32_t sdst, const void* gsrc,
                                          uint32_t sz) {
    asm volatile("cp.async.cg.shared.global [%0], [%1], 16, %2;"
                 :: "r"(sdst), "l"(gsrc), "r"(sz));
}
__device__ __forceinline__ void cpcommit() {
    asm volatile("cp.async.commit_group;");
}
template <int N>
__device__ __forceinline__ void cpwait() {
    asm volatile("cp.async.wait_group %0;" :: "n"(N));
}
__device__ __forceinline__ float sigmoidf_(float x) {
    return 1.f / (1.f + expf(-x));
}

// ---------------------------------------------------------------------------
// All-weights transpose + fp16 hi/lo split in ONE launch
// ---------------------------------------------------------------------------
__global__ __launch_bounds__(256) void wsplit_all_kernel(
    const float* __restrict__ W1, const float* __restrict__ G1,
    const float* __restrict__ W2, const float* __restrict__ G2,
    __half* __restrict__ w1h, __half* __restrict__ w1l,
    __half* __restrict__ g1h, __half* __restrict__ g1l,
    __half* __restrict__ w2h, __half* __restrict__ w2l,
    __half* __restrict__ g2h, __half* __restrict__ g2l)
{
    int i = blockIdx.x * blockDim.x + threadIdx.x;
    const float* src; __half *hi, *lo; int local, N;
    if (i < 65536)        { src = W1; hi = w1h; lo = w1l; local = i;          N = 256; }
    else if (i < 131072)  { src = G1; hi = g1h; lo = g1l; local = i - 65536;  N = 256; }
    else if (i < 163840)  { src = W2; hi = w2h; lo = w2l; local = i - 131072; N = 128; }
    else if (i < 196608)  { src = G2; hi = g2h; lo = g2l; local = i - 163840; N = 128; }
    else return;
    int n = local >> 8, k = local & 255;
    float w = src[(size_t)k * N + n];
    __half h = __float2half_rn(w);
    hi[local] = h;
    lo[local] = __float2half_rn(w - __half2float(h));
}

// ---------------------------------------------------------------------------
// CSR build: histogram -> scan (2 kernels) -> scatter (atomicSub on cnt)
// ---------------------------------------------------------------------------
__global__ __launch_bounds__(256) void hist_kernel(
    const int* __restrict__ rows, int* __restrict__ cnt, int E)
{
    int e = blockIdx.x * blockDim.x + threadIdx.x;
    if (e < E) atomicAdd(&cnt[rows[e]], 1);
}

__global__ __launch_bounds__(1024) void scanA_kernel(
    const int* __restrict__ cnt, int* __restrict__ rowptr,
    int* __restrict__ blk, int n)
{
    __shared__ int warp_sums[32];
    const int tid = threadIdx.x, lane = tid & 31, w = tid >> 5;
    int i = blockIdx.x * 1024 + tid;
    int v = (i < n) ? cnt[i] : 0;
    int s = v;
#pragma unroll
    for (int o = 1; o < 32; o <<= 1) {
        int t = __shfl_up_sync(0xffffffffu, s, o);
        if (lane >= o) s += t;
    }
    if (lane == 31) warp_sums[w] = s;
    __syncthreads();
    if (w == 0) {
        int ws = warp_sums[lane];
#pragma unroll
        for (int o = 1; o < 32; o <<= 1) {
            int t = __shfl_up_sync(0xffffffffu, ws, o);
            if (lane >= o) ws += t;
        }
        warp_sums[lane] = ws;
    }
    __syncthreads();
    int incl = s + (w > 0 ? warp_sums[w - 1] : 0);
    if (i < n) rowptr[i + 1] = incl;
    if (tid == 1023) blk[blockIdx.x] = incl;
}

// scanC with inline block-offset reduction (folds old scanB)
__global__ __launch_bounds__(1024) void scanC_kernel(
    int* __restrict__ rowptr, const int* __restrict__ blk, int n, int nb)
{
    __shared__ int tmp[64];
    __shared__ int s_off;
    const int tid = threadIdx.x;
    if (tid < 64) tmp[tid] = (tid < (int)blockIdx.x && tid < nb) ? blk[tid] : 0;
    __syncthreads();
    if (tid < 32) {
        int v = tmp[tid] + tmp[tid + 32];
#pragma unroll
        for (int o = 16; o > 0; o >>= 1)
            v += __shfl_down_sync(0xffffffffu, v, o);
        if (tid == 0) s_off = v;
    }
    __syncthreads();
    int i = blockIdx.x * 1024 + tid;
    if (i < n) rowptr[i + 1] += s_off;
    if (i == 0) rowptr[0] = 0;
}

// scatter: pos = rowptr[r] + (atomicSub(cnt[r]) - 1); cnt ends at 0.
__global__ __launch_bounds__(256) void scatter_kernel(
    const int* __restrict__ rows, const int* __restrict__ cols,
    const float* __restrict__ vals,
    const int* __restrict__ rowptr, int* __restrict__ cnt,
    int2* __restrict__ edges, int E)
{
    int e = blockIdx.x * blockDim.x + threadIdx.x;
    if (e >= E) return;
    int r = rows[e];
    int old = atomicSub(&cnt[r], 1);
    edges[rowptr[r] + old - 1] = make_int2(cols[e], __float_as_int(vals[e]));
}

// ---------------------------------------------------------------------------
// SpMM #1: X fp32 -> Z fp16.  64 thr/row (each one float4), 4 rows/block.
// ---------------------------------------------------------------------------
__global__ __launch_bounds__(256) void spmm_f32_kernel(
    const int*  __restrict__ rowptr, const int2* __restrict__ edges,
    const float4* __restrict__ X, __half* __restrict__ Z, int n)
{
    const int r = blockIdx.x * 4 + (threadIdx.x >> 6);
    const int j = threadIdx.x & 63;
    if (r >= n) return;

    const int beg = __ldg(&rowptr[r]);
    const int end = __ldg(&rowptr[r + 1]);

    float4 a = make_float4(0.f, 0.f, 0.f, 0.f);
    int i = beg;
    for (; i + 3 < end; i += 4) {
        int2 e0 = __ldg(&edges[i]);
        int2 e1 = __ldg(&edges[i + 1]);
        int2 e2 = __ldg(&edges[i + 2]);
        int2 e3 = __ldg(&edges[i + 3]);
        float4 s0 = __ldg(&X[(size_t)e0.x * 64 + j]);
        float4 s1 = __ldg(&X[(size_t)e1.x * 64 + j]);
        float4 s2 = __ldg(&X[(size_t)e2.x * 64 + j]);
        float4 s3 = __ldg(&X[(size_t)e3.x * 64 + j]);
        float v0 = __int_as_float(e0.y), v1 = __int_as_float(e1.y);
        float v2 = __int_as_float(e2.y), v3 = __int_as_float(e3.y);
        a.x = fmaf(v0, s0.x, a.x); a.y = fmaf(v0, s0.y, a.y);
        a.z = fmaf(v0, s0.z, a.z); a.w = fmaf(v0, s0.w, a.w);
        a.x = fmaf(v1, s1.x, a.x); a.y = fmaf(v1, s1.y, a.y);
        a.z = fmaf(v1, s1.z, a.z); a.w = fmaf(v1, s1.w, a.w);
        a.x = fmaf(v2, s2.x, a.x); a.y = fmaf(v2, s2.y, a.y);
        a.z = fmaf(v2, s2.z, a.z); a.w = fmaf(v2, s2.w, a.w);
        a.x = fmaf(v3, s3.x, a.x); a.y = fmaf(v3, s3.y, a.y);
        a.z = fmaf(v3, s3.z, a.z); a.w = fmaf(v3, s3.w, a.w);
    }
    for (; i < end; i++) {
        int2 e = __ldg(&edges[i]);
        const float v = __int_as_float(e.y);
        float4 s = __ldg(&X[(size_t)e.x * 64 + j]);
        a.x = fmaf(v, s.x, a.x); a.y = fmaf(v, s.y, a.y);
        a.z = fmaf(v, s.z, a.z); a.w = fmaf(v, s.w, a.w);
    }

    __half2 p0 = __floats2half2_rn(a.x, a.y);
    __half2 p1 = __floats2half2_rn(a.z, a.w);
    *reinterpret_cast<uint2*>(&Z[(size_t)r * 256 + j * 4]) =
        make_uint2(*(uint32_t*)&p0, *(uint32_t*)&p1);
}

// ---------------------------------------------------------------------------
// SpMM #2: X fp16 -> Z fp16.  32 thr/row (each 8 halves = 16B), 8 rows/block.
// Gather traffic halved vs fp32.
// ---------------------------------------------------------------------------
__global__ __launch_bounds__(256) void spmm_f16_kernel(
    const int*  __restrict__ rowptr, const int2* __restrict__ edges,
    const uint4* __restrict__ X, uint4* __restrict__ Z, int n)
{
    const int r = blockIdx.x * 8 + (threadIdx.x >> 5);
    const int j = threadIdx.x & 31;
    if (r >= n) return;

    const int beg = __ldg(&rowptr[r]);
    const int end = __ldg(&rowptr[r + 1]);

    float a[8];
#pragma unroll
    for (int q = 0; q < 8; q++) a[q] = 0.f;

    auto accum = [&](int2 e) {
        const float v = __int_as_float(e.y);
        uint4 q = __ldg(&X[(size_t)e.x * 32 + j]);
        const __half2* hp = reinterpret_cast<const __half2*>(&q);
#pragma unroll
        for (int p = 0; p < 4; p++) {
            float2 f = __half22float2(hp[p]);
            a[2 * p]     = fmaf(v, f.x, a[2 * p]);
            a[2 * p + 1] = fmaf(v, f.y, a[2 * p + 1]);
        }
    };

    int i = beg;
    for (; i + 3 < end; i += 4) {
        int2 e0 = __ldg(&edges[i]);
        int2 e1 = __ldg(&edges[i + 1]);
        int2 e2 = __ldg(&edges[i + 2]);
        int2 e3 = __ldg(&edges[i + 3]);
        accum(e0); accum(e1); accum(e2); accum(e3);
    }
    for (; i < end; i++) accum(__ldg(&edges[i]));

    __half2 p0 = __floats2half2_rn(a[0], a[1]);
    __half2 p1 = __floats2half2_rn(a[2], a[3]);
    __half2 p2 = __floats2half2_rn(a[4], a[5]);
    __half2 p3 = __floats2half2_rn(a[6], a[7]);
    uint4 o = make_uint4(*(uint32_t*)&p0, *(uint32_t*)&p1,
                         *(uint32_t*)&p2, *(uint32_t*)&p3);
    Z[(size_t)r * 32 + j] = o;
}

// ---------------------------------------------------------------------------
// Fused gated dual-GEMM:  O = act( sigmoid(Z@G) * (Z@W) )
//   Z: [M,256] fp16 (single). W/G: [NOUT,256] fp16 hi+lo, K-major.
//   CTA 128 rows x 128 cols, 512 threads / 16 warps. Warp tile 32x32 per
//   output = 2x4 m16n8 tiles, 2 MMA terms per output (zh*bh + zh*bl).
//   KC=64, 2-stage cp.async, ldmatrix, ROW=72-half padding (conflict-free).
// ---------------------------------------------------------------------------
template <int NOUT, bool RELU, bool OUT_HALF>
__global__ __launch_bounds__(512, 1) void gemm_gated_kernel(
    const __half* __restrict__ A,
    const __half* __restrict__ Wh, const __half* __restrict__ Wl,
    const __half* __restrict__ Gh, const __half* __restrict__ Gl,
    void* __restrict__ O, int M)
{
    constexpr int K = 256, KC = 64, NCH = K / KC;
    constexpr int ROW  = 72;                        // padded row (halves)
    constexpr int TMAT = 128 * ROW;                 // 9216 halves per matrix
    constexpr int B0   = TMAT;                      // after A
    constexpr int STG  = 5 * TMAT;                  // A + 4 B matrices

    extern __shared__ __align__(16) __half dsm[];
    const uint32_t sb = (uint32_t)__cvta_generic_to_shared(dsm);

    const int tid  = threadIdx.x;
    const int wid  = tid >> 5;
    const int lane = tid & 31;
    const int warp_m = wid & 3;
    const int warp_n = wid >> 2;
    const int row0 = blockIdx.y * 128;
    const int col0 = blockIdx.x * 128;

    const __half* bsrc[4] = {Wh, Wl, Gh, Gl};

    auto load_stage = [&](int s, int c) {
        const int k0 = c * KC;
        const uint32_t base = sb + (uint32_t)(s * STG) * 2;
#pragma unroll
        for (int it = 0; it < 2; it++) {            // A: 1024 vec16
            int i = tid + it * 512;
            int r = i >> 3, v = i & 7;
            int grow = row0 + r;
            uint32_t sz = (grow < M) ? 16u : 0u;
            int gclamp = (grow < M) ? grow : (M - 1);
            size_t go = (size_t)gclamp * K + k0 + v * 8;
            uint32_t so = (uint32_t)(r * ROW + v * 8) * 2;
            cpasync16(base + so, &A[go], sz);
        }
#pragma unroll
        for (int m = 0; m < 4; m++) {               // B: 4 x 1024 vec16
#pragma unroll
            for (int it = 0; it < 2; it++) {
                int i = tid + it * 512;
                int r = i >> 3, v = i & 7;
                size_t go = (size_t)(col0 + r) * K + k0 + v * 8;
                uint32_t so = (uint32_t)(B0 + m * TMAT + r * ROW + v * 8) * 2;
                cpasync16(base + so, &bsrc[m][go], 16u);
            }
        }
        cpcommit();
    };

    float accS[2][4][4], accT[2][4][4];
#pragma unroll
    for (int i = 0; i < 2; i++)
#pragma unroll
        for (int j = 0; j < 4; j++)
#pragma unroll
            for (int q = 0; q < 4; q++) { accS[i][j][q] = 0.f; accT[i][j][q] = 0.f; }

    load_stage(0, 0);

    for (int c = 0; c < NCH; c++) {
        if (c + 1 < NCH) {
            load_stage((c + 1) & 1, c + 1);
            cpwait<1>();
        } else {
            cpwait<0>();
        }
        __syncthreads();

        const uint32_t base = sb + (uint32_t)((c & 1) * STG) * 2;
#pragma unroll
        for (int ks = 0; ks < KC / 16; ks++) {
            uint32_t ah[2][4];
#pragma unroll
            for (int mt = 0; mt < 2; mt++) {
                uint32_t ra = base + (uint32_t)(
                    (warp_m * 32 + mt * 16 + (lane & 15)) * ROW +
                    ks * 16 + (lane >> 4) * 8) * 2;
                ldmx4(ah[mt], ra);
            }
            uint32_t wh[4][2], wl[4][2], gh[4][2], gl[4][2];
#pragma unroll
            for (int nt = 0; nt < 4; nt++) {
                uint32_t rb = base + (uint32_t)(B0 +
                    (warp_n * 32 + nt * 8 + (lane & 7)) * ROW +
                    ks * 16 + ((lane >> 3) & 1) * 8) * 2;
                ldmx2(wh[nt], rb);
                ldmx2(wl[nt], rb + (uint32_t)TMAT * 2);
                ldmx2(gh[nt], rb + (uint32_t)(2 * TMAT) * 2);
                ldmx2(gl[nt], rb + (uint32_t)(3 * TMAT) * 2);
            }
#pragma unroll
            for (int mt = 0; mt < 2; mt++)
#pragma unroll
                for (int nt = 0; nt < 4; nt++) {
                    mma16816(accS[mt][nt], ah[mt], wh[nt]);
                    mma16816(accS[mt][nt], ah[mt], wl[nt]);
                    mma16816(accT[mt][nt], ah[mt], gh[nt]);
                    mma16816(accT[mt][nt], ah[mt], gl[nt]);
                }
        }
        __syncthreads();
    }

    // ---- gated epilogue ----
#pragma unroll
    for (int mt = 0; mt < 2; mt++) {
        int r_lo = row0 + warp_m * 32 + mt * 16 + (lane >> 2);
#pragma unroll
        for (int nt = 0; nt < 4; nt++) {
            int n = col0 + warp_n * 32 + nt * 8 + (lane & 3) * 2;
            float o0 = sigmoidf_(accT[mt][nt][0]) * accS[mt][nt][0];
            float o1 = sigmoidf_(accT[mt][nt][1]) * accS[mt][nt][1];
            float o2 = sigmoidf_(accT[mt][nt][2]) * accS[mt][nt][2];
            float o3 = sigmoidf_(accT[mt][nt][3]) * accS[mt][nt][3];
            if (RELU) {
                o0 = fmaxf(o0, 0.f); o1 = fmaxf(o1, 0.f);
                o2 = fmaxf(o2, 0.f); o3 = fmaxf(o3, 0.f);
            }
            if (OUT_HALF) {
                __half* Oh = (__half*)O;
                __half2 lo = __floats2half2_rn(o0, o1);
                __half2 hi = __floats2half2_rn(o2, o3);
                if (r_lo < M)
                    *reinterpret_cast<__half2*>(&Oh[(size_t)r_lo * NOUT + n]) = lo;
                if (r_lo + 8 < M)
                    *reinterpret_cast<__half2*>(&Oh[(size_t)(r_lo + 8) * NOUT + n]) = hi;
            } else {
                float* Of = (float*)O;
                if (r_lo < M)
                    *reinterpret_cast<float2*>(&Of[(size_t)r_lo * NOUT + n]) =
                        make_float2(o0, o1);
                if (r_lo + 8 < M)
                    *reinterpret_cast<float2*>(&Of[(size_t)(r_lo + 8) * NOUT + n]) =
                        make_float2(o2, o3);
            }
        }
    }
}

// ---------------------------------------------------------------------------
// Launcher (graph-capturable)
// ---------------------------------------------------------------------------
extern "C" void kernel_launch(void* const* d_in, const int* in_sizes, int n_in,
                              void* d_out, int out_size)
{
    const float* x    = (const float*)d_in[0];
    const int*   rows = (const int*)  d_in[1];
    const int*   cols = (const int*)  d_in[2];
    const float* vals = (const float*)d_in[3];
    const float* W1   = (const float*)d_in[4];
    const float* G1   = (const float*)d_in[5];
    const float* W2   = (const float*)d_in[6];
    const float* G2   = (const float*)d_in[7];
    float* out = (float*)d_out;

    __half *Z, *h, *w1h, *w1l, *g1h, *g1l, *w2h, *w2l, *g2h, *g2l;
    int *rowptr, *cnt, *blk;
    int2 *edges;
    cudaGetSymbolAddress((void**)&Z,      g_Z);
    cudaGetSymbolAddress((void**)&h,      g_h);
    cudaGetSymbolAddress((void**)&w1h,    g_w1h);
    cudaGetSymbolAddress((void**)&w1l,    g_w1l);
    cudaGetSymbolAddress((void**)&g1h,    g_g1h);
    cudaGetSymbolAddress((void**)&g1l,    g_g1l);
    cudaGetSymbolAddress((void**)&w2h,    g_w2h);
    cudaGetSymbolAddress((void**)&w2l,    g_w2l);
    cudaGetSymbolAddress((void**)&g2h,    g_g2h);
    cudaGetSymbolAddress((void**)&g2l,    g_g2l);
    cudaGetSymbolAddress((void**)&rowptr, g_rowptr);
    cudaGetSymbolAddress((void**)&cnt,    g_cnt);
    cudaGetSymbolAddress((void**)&blk,    g_blk);
    cudaGetSymbolAddress((void**)&edges,  g_edges);

    const int M  = N_NODES;
    const int EB = (E_EDGES + 255) / 256;
    const int MT = (M + 127) / 128;                 // 391 M-tiles
    const int NB = (M + 1023) / 1024;               // 49 scan blocks

    constexpr int GSMEM = 2 * 5 * 9216 * 2;         // 184320 B
    cudaFuncSetAttribute(gemm_gated_kernel<D_HID, true, true>,
                         cudaFuncAttributeMaxDynamicSharedMemorySize, GSMEM);
    cudaFuncSetAttribute(gemm_gated_kernel<D_OUT, false, false>,
                         cudaFuncAttributeMaxDynamicSharedMemorySize, GSMEM);

    // -------- CSR build --------
    cudaMemsetAsync(cnt, 0, N_NODES * sizeof(int));
    hist_kernel<<<EB, 256>>>(rows, cnt, E_EDGES);
    scanA_kernel<<<NB, 1024>>>(cnt, rowptr, blk, N_NODES);
    scanC_kernel<<<NB, 1024>>>(rowptr, blk, N_NODES, NB);
    scatter_kernel<<<EB, 256>>>(rows, cols, vals, rowptr, cnt, edges, E_EDGES);

    // -------- weight prep (one launch) --------
    wsplit_all_kernel<<<768, 256>>>(W1, G1, W2, G2,
                                    w1h, w1l, g1h, g1l, w2h, w2l, g2h, g2l);

    // -------- Layer 1: Z = spmm(adj, x); h = relu(sig(Z@G1)*(Z@W1)) --------
    spmm_f32_kernel<<<(M + 3) / 4, 256>>>(rowptr, edges, (const float4*)x, Z, M);
    gemm_gated_kernel<D_HID, true, true><<<dim3(D_HID / 128, MT), 512, GSMEM>>>(
        Z, w1h, w1l, g1h, g1l, h, M);

    // -------- Layer 2: Z = spmm(adj, h); out = sig(Z@G2)*(Z@W2) --------
    spmm_f16_kernel<<<(M + 7) / 8, 256>>>(rowptr, edges, (const uint4*)h,
                                          (uint4*)Z, M);
    gemm_gated_kernel<D_OUT, false, false><<<dim3(D_OUT / 128, MT), 512, GSMEM>>>(
        Z, w2h, w2l, g2h, g2l, out, M);
}